// round 3
// baseline (speedup 1.0000x reference)
#include <cuda_runtime.h>
#include <math.h>

#define F_DIM 128
#define NRBF  20
#define MAXN  10000
#define MAXE  320000
#define NLAYERS 3

typedef unsigned long long u64;

// ---------------- packed f32x2 helpers (sm_103a FFMA2) ----------------
__device__ __forceinline__ u64 ffma2(u64 a, u64 b, u64 c) {
    u64 d;
    asm("fma.rn.f32x2 %0, %1, %2, %3;" : "=l"(d) : "l"(a), "l"(b), "l"(c));
    return d;
}
__device__ __forceinline__ u64 pack2(float lo, float hi) {
    u64 d;
    asm("mov.b64 %0, {%1, %2};" : "=l"(d) : "f"(lo), "f"(hi));
    return d;
}
__device__ __forceinline__ float2 unpack2(u64 v) {
    float lo, hi;
    asm("mov.b64 {%0, %1}, %2;" : "=f"(lo), "=f"(hi) : "l"(v));
    return make_float2(lo, hi);
}

// ---------------- device scratch (allocation-free) ----------------
__device__ float g_dir  [MAXE * 3];
__device__ float g_phif [MAXE * NRBF];   // phi * fcut  (rows are 80B -> 16B aligned)
__device__ float g_fcut [MAXE];
__device__ int   g_rowptr[MAXN + 1];
__device__ float g_x    [MAXN * 384];    // interaction x, reused for mixing x2
__device__ float g_h    [MAXN * 128];
__device__ float g_muA  [MAXN * 384];    // ping-pong partner of d_out mu region
__device__ float g_mumix[MAXN * 768];    // [N,3,256]
__device__ float g_ctx  [MAXN * 256];
__device__ float g_s    [MAXN * 128];

// ---------------- precompute per-edge geometry + RBF ----------------
__global__ void pre_kernel(const float* __restrict__ r_ij, int E) {
    int e = blockIdx.x * blockDim.x + threadIdx.x;
    if (e >= E) return;
    float x = r_ij[e * 3 + 0];
    float y = r_ij[e * 3 + 1];
    float z = r_ij[e * 3 + 2];
    float d = sqrtf(x * x + y * y + z * z);
    float inv = 1.0f / d;
    g_dir[e * 3 + 0] = x * inv;
    g_dir[e * 3 + 1] = y * inv;
    g_dir[e * 3 + 2] = z * inv;
    float fc = (d < 5.0f) ? 0.5f * (cosf(d * 0.62831853071795864769f) + 1.0f) : 0.0f;
    g_fcut[e] = fc;
    const float delta = 5.0f / 19.0f;
    const float coeff = -0.5f / (delta * delta);
#pragma unroll
    for (int r = 0; r < NRBF; r++) {
        float diff = d - delta * (float)r;
        g_phif[e * NRBF + r] = expf(coeff * diff * diff) * fc;
    }
}

// ---------------- segment boundaries (idx_i sorted) ----------------
__global__ void rowptr_kernel(const int* __restrict__ idx_i, int E, int N) {
    int i = blockIdx.x * blockDim.x + threadIdx.x;
    if (i > N) return;
    int lo = 0, hi = E;
    while (lo < hi) {
        int mid = (lo + hi) >> 1;
        if (idx_i[mid] < i) lo = mid + 1; else hi = mid;
    }
    g_rowptr[i] = lo;
}

// ---------------- init q = embedding[an], muA = 0 ----------------
__global__ void init_kernel(const int* __restrict__ an, const float* __restrict__ emb,
                            float* __restrict__ q, int N) {
    int t = blockIdx.x * blockDim.x + threadIdx.x;
    if (t < N * 384) g_muA[t] = 0.0f;
    if (t < N * 128) {
        int n = t >> 7, c = t & 127;
        q[t] = emb[an[n] * 128 + c];
    }
}

// ---------------- double-buffered fp32 GEMM (FFMA2 inner loop) ------------
// C = act(A[M,K] @ W[K,N] + bias). BM=BN=64, BK=16, 256 threads, 4x4/thread.
template <int ACT>   // 0 = none, 1 = silu
__global__ void __launch_bounds__(256)
gemm64(const float* __restrict__ A, const float* __restrict__ W,
       const float* __restrict__ bias, float* __restrict__ C,
       int M, int N, int K) {
    __shared__ __align__(16) float As[2][16][68];   // [buf][k][m]
    __shared__ __align__(16) float Bs[2][16][68];   // [buf][k][n]
    const int tid  = threadIdx.x;
    const int row0 = blockIdx.y * 64;
    const int col0 = blockIdx.x * 64;
    const int tx = tid & 15, ty = tid >> 4;
    const int ar = tid >> 2;            // 0..63 (A row within tile)
    const int ak = (tid & 3) << 2;      // 0,4,8,12 (k offset)
    const int br = tid >> 4;            // 0..15 (B k-row)
    const int bc = (tid & 15) << 2;     // 0..60 (B col offset)

    const float* Aptr = A + (size_t)(row0 + ar) * K + ak;
    const bool aval = (row0 + ar) < M;

    float4 aReg = aval ? *(const float4*)Aptr : make_float4(0.f, 0.f, 0.f, 0.f);
    float4 bReg = *(const float4*)&W[(size_t)br * N + col0 + bc];
    As[0][ak + 0][ar] = aReg.x; As[0][ak + 1][ar] = aReg.y;
    As[0][ak + 2][ar] = aReg.z; As[0][ak + 3][ar] = aReg.w;
    *(float4*)&Bs[0][br][bc] = bReg;
    __syncthreads();

    u64 acc2[4][2];
#pragma unroll
    for (int i = 0; i < 4; i++) { acc2[i][0] = 0ull; acc2[i][1] = 0ull; }

    int buf = 0;
    for (int k0 = 16; k0 < K; k0 += 16) {
        // prefetch next tile into registers
        aReg = aval ? *(const float4*)(Aptr + k0) : make_float4(0.f, 0.f, 0.f, 0.f);
        bReg = *(const float4*)&W[(size_t)(k0 + br) * N + col0 + bc];
        // compute current buffer
#pragma unroll
        for (int kk = 0; kk < 16; kk++) {
            float4 av = *(const float4*)&As[buf][kk][ty << 2];
            ulonglong2 bv = *(const ulonglong2*)&Bs[buf][kk][tx << 2];
            u64 a0 = pack2(av.x, av.x), a1 = pack2(av.y, av.y);
            u64 a2 = pack2(av.z, av.z), a3 = pack2(av.w, av.w);
            acc2[0][0] = ffma2(a0, bv.x, acc2[0][0]); acc2[0][1] = ffma2(a0, bv.y, acc2[0][1]);
            acc2[1][0] = ffma2(a1, bv.x, acc2[1][0]); acc2[1][1] = ffma2(a1, bv.y, acc2[1][1]);
            acc2[2][0] = ffma2(a2, bv.x, acc2[2][0]); acc2[2][1] = ffma2(a2, bv.y, acc2[2][1]);
            acc2[3][0] = ffma2(a3, bv.x, acc2[3][0]); acc2[3][1] = ffma2(a3, bv.y, acc2[3][1]);
        }
        // store prefetched tile into the other buffer
        buf ^= 1;
        As[buf][ak + 0][ar] = aReg.x; As[buf][ak + 1][ar] = aReg.y;
        As[buf][ak + 2][ar] = aReg.z; As[buf][ak + 3][ar] = aReg.w;
        *(float4*)&Bs[buf][br][bc] = bReg;
        __syncthreads();
    }
    // final tile
#pragma unroll
    for (int kk = 0; kk < 16; kk++) {
        float4 av = *(const float4*)&As[buf][kk][ty << 2];
        ulonglong2 bv = *(const ulonglong2*)&Bs[buf][kk][tx << 2];
        u64 a0 = pack2(av.x, av.x), a1 = pack2(av.y, av.y);
        u64 a2 = pack2(av.z, av.z), a3 = pack2(av.w, av.w);
        acc2[0][0] = ffma2(a0, bv.x, acc2[0][0]); acc2[0][1] = ffma2(a0, bv.y, acc2[0][1]);
        acc2[1][0] = ffma2(a1, bv.x, acc2[1][0]); acc2[1][1] = ffma2(a1, bv.y, acc2[1][1]);
        acc2[2][0] = ffma2(a2, bv.x, acc2[2][0]); acc2[2][1] = ffma2(a2, bv.y, acc2[2][1]);
        acc2[3][0] = ffma2(a3, bv.x, acc2[3][0]); acc2[3][1] = ffma2(a3, bv.y, acc2[3][1]);
    }

    // epilogue
#pragma unroll
    for (int i = 0; i < 4; i++) {
        int r = row0 + (ty << 2) + i;
        if (r >= M) continue;
        float2 c01 = unpack2(acc2[i][0]);
        float2 c23 = unpack2(acc2[i][1]);
        float vals[4] = {c01.x, c01.y, c23.x, c23.y};
        float4 v;
        float* pv = &v.x;
#pragma unroll
        for (int j = 0; j < 4; j++) {
            float val = vals[j];
            if (bias) val += bias[col0 + (tx << 2) + j];
            if (ACT == 1) val = val / (1.0f + expf(-val));
            pv[j] = val;
        }
        *(float4*)&C[(size_t)r * N + col0 + (tx << 2)] = v;
    }
}

// ---------------- edge message + segment-sum kernel ----------------
// One block (128 threads) per node. Thread c owns feature c.
// Filter weights r-paired into f32x2 registers (loop-invariant);
// phif rows loaded directly as packed f32x2 pairs (80B rows, 16B aligned).
__global__ void __launch_bounds__(128)
edge_kernel(const float* __restrict__ x,
            float* __restrict__ q,
            const float* __restrict__ mu_in,
            float* __restrict__ mu_out,
            const int* __restrict__ idx_j,
            const float* __restrict__ filt_W,
            const float* __restrict__ filt_b,
            int layer, int N) {
    int c = threadIdx.x;   // 0..127
    int layOff = layer * 384;
    u64 WQ2[10], WR2[10], WM2[10];
#pragma unroll
    for (int r2 = 0; r2 < 10; r2++) {
        const float* f0 = &filt_W[(2 * r2)     * (NLAYERS * 384) + layOff];
        const float* f1 = &filt_W[(2 * r2 + 1) * (NLAYERS * 384) + layOff];
        WQ2[r2] = pack2(f0[c],       f1[c]);
        WR2[r2] = pack2(f0[128 + c], f1[128 + c]);
        WM2[r2] = pack2(f0[256 + c], f1[256 + c]);
    }
    float FBq = filt_b[layOff + c];
    float FBr = filt_b[layOff + 128 + c];
    float FBm = filt_b[layOff + 256 + c];

    int node = blockIdx.x;
    if (node >= N) return;
    int e0 = g_rowptr[node], e1 = g_rowptr[node + 1];
    float accq = 0.f, am0 = 0.f, am1 = 0.f, am2 = 0.f;
    for (int e = e0; e < e1; e++) {
        int j = idx_j[e];
        // phif row as 10 packed f32x2 (5 x 16B vector loads)
        u64 p2[10];
        const ulonglong2* pp = (const ulonglong2*)&g_phif[(size_t)e * NRBF];
#pragma unroll
        for (int v = 0; v < 5; v++) {
            ulonglong2 t = pp[v];
            p2[2 * v]     = t.x;
            p2[2 * v + 1] = t.y;
        }
        float fc = g_fcut[e];
        u64 aq = pack2(fc * FBq, 0.f);
        u64 ar = pack2(fc * FBr, 0.f);
        u64 am = pack2(fc * FBm, 0.f);
#pragma unroll
        for (int r = 0; r < 10; r++) {
            aq = ffma2(p2[r], WQ2[r], aq);
            ar = ffma2(p2[r], WR2[r], ar);
            am = ffma2(p2[r], WM2[r], am);
        }
        float2 fq = unpack2(aq), fr = unpack2(ar), fm = unpack2(am);
        float Wq = fq.x + fq.y, Wr = fr.x + fr.y, Wm = fm.x + fm.y;

        const float* xr = &x[(size_t)j * 384];
        float xq = xr[c], xR = xr[128 + c], xM = xr[256 + c];
        float d0 = g_dir[e * 3 + 0], d1 = g_dir[e * 3 + 1], d2 = g_dir[e * 3 + 2];
        accq = fmaf(Wq, xq, accq);
        float t   = Wr * xR;
        float wmx = Wm * xM;
        const float* mj = &mu_in[(size_t)j * 384];
        am0 = fmaf(t, d0, fmaf(wmx, mj[c],       am0));
        am1 = fmaf(t, d1, fmaf(wmx, mj[128 + c], am1));
        am2 = fmaf(t, d2, fmaf(wmx, mj[256 + c], am2));
    }
    q[(size_t)node * 128 + c] += accq;
    size_t mb = (size_t)node * 384;
    mu_out[mb + c]       = mu_in[mb + c]       + am0;
    mu_out[mb + 128 + c] = mu_in[mb + 128 + c] + am1;
    mu_out[mb + 256 + c] = mu_in[mb + 256 + c] + am2;
}

// ---------------- mixing stage 1: norms, dot, build ctx ----------------
__global__ void mix1_kernel(const float* __restrict__ q, int N) {
    int t = blockIdx.x * blockDim.x + threadIdx.x;
    if (t >= N * 128) return;
    int n = t >> 7, c = t & 127;
    const float* mm = &g_mumix[(size_t)n * 768];
    float v0 = mm[c],        v1 = mm[256 + c], v2 = mm[512 + c];
    float w0 = mm[128 + c],  w1 = mm[384 + c], w2 = mm[640 + c];
    float vn = sqrtf(v0 * v0 + v1 * v1 + v2 * v2 + 1e-8f);
    g_ctx[(size_t)n * 256 + c]       = q[t];
    g_ctx[(size_t)n * 256 + 128 + c] = vn;
    g_s[t] = v0 * w0 + v1 * w1 + v2 * w2;
}

// ---------------- mixing stage 2: final per-node update ----------------
__global__ void epi2_kernel(float* __restrict__ q, float* __restrict__ mu, int N) {
    int t = blockIdx.x * blockDim.x + threadIdx.x;
    if (t >= N * 128) return;
    int n = t >> 7, c = t & 127;
    const float* xr = &g_x[(size_t)n * 384];
    float dq   = xr[c];
    float dmu  = xr[128 + c];
    float dqmu = xr[256 + c];
    q[t] += dq + dqmu * g_s[t];
    const float* mm = &g_mumix[(size_t)n * 768];
    size_t mb = (size_t)n * 384;
    mu[mb + c]       += dmu * mm[128 + c];
    mu[mb + 128 + c] += dmu * mm[384 + c];
    mu[mb + 256 + c] += dmu * mm[640 + c];
}

// ---------------- host launch ----------------
extern "C" void kernel_launch(void* const* d_in, const int* in_sizes, int n_in,
                              void* d_out, int out_size) {
    const int*   an     = (const int*)  d_in[0];
    const float* r_ij   = (const float*)d_in[1];
    const int*   idx_i  = (const int*)  d_in[2];
    const int*   idx_j  = (const int*)  d_in[3];
    const float* emb    = (const float*)d_in[4];
    const float* filt_W = (const float*)d_in[5];
    const float* filt_b = (const float*)d_in[6];
    const float* int_W1 = (const float*)d_in[7];
    const float* int_b1 = (const float*)d_in[8];
    const float* int_W2 = (const float*)d_in[9];
    const float* int_b2 = (const float*)d_in[10];
    const float* mix_W1 = (const float*)d_in[11];
    const float* mix_b1 = (const float*)d_in[12];
    const float* mix_W2 = (const float*)d_in[13];
    const float* mix_b2 = (const float*)d_in[14];
    const float* mux_W  = (const float*)d_in[15];

    int N = in_sizes[0];
    int E = in_sizes[3];

    float* q      = (float*)d_out;          // [N,128]
    float* mu_out = q + (size_t)N * 128;    // [N,3,128]

    void* pA; cudaGetSymbolAddress(&pA, g_muA);  float* muA  = (float*)pA;
    void* pH; cudaGetSymbolAddress(&pH, g_h);    float* h    = (float*)pH;
    void* pX; cudaGetSymbolAddress(&pX, g_x);    float* xbuf = (float*)pX;
    void* pM; cudaGetSymbolAddress(&pM, g_mumix);float* mumix= (float*)pM;
    void* pC; cudaGetSymbolAddress(&pC, g_ctx);  float* ctx  = (float*)pC;

    // precompute
    pre_kernel   <<<(E + 255) / 256, 256>>>(r_ij, E);
    rowptr_kernel<<<(N + 256) / 256, 256>>>(idx_i, E, N);
    init_kernel  <<<((size_t)N * 384 + 255) / 256, 256>>>(an, emb, q, N);

    for (int l = 0; l < NLAYERS; l++) {
        float* mu_in = (l & 1) ? mu_out : muA;
        float* mu_o  = (l & 1) ? muA    : mu_out;

        // interaction: h = silu(q W1 + b1); x = h W2 + b2
        {
            dim3 g(128 / 64, (N + 63) / 64);
            gemm64<1><<<g, 256>>>(q, int_W1 + (size_t)l * 128 * 128,
                                  int_b1 + l * 128, h, N, 128, 128);
        }
        {
            dim3 g(384 / 64, (N + 63) / 64);
            gemm64<0><<<g, 256>>>(h, int_W2 + (size_t)l * 128 * 384,
                                  int_b2 + l * 384, xbuf, N, 384, 128);
        }
        // edge messages + segment sum (one block per node)
        edge_kernel<<<N, 128>>>(xbuf, q, mu_in, mu_o, idx_j,
                                filt_W, filt_b, l, N);
        // mixing: mumix = mu @ mux_W (no bias), A viewed as [3N,128]
        {
            dim3 g(256 / 64, (3 * N + 63) / 64);
            gemm64<0><<<g, 256>>>(mu_o, mux_W + (size_t)l * 128 * 256,
                                  nullptr, mumix, 3 * N, 256, 128);
        }
        mix1_kernel<<<((size_t)N * 128 + 255) / 256, 256>>>(q, N);
        // h = silu(ctx mix_W1 + b1)
        {
            dim3 g(128 / 64, (N + 63) / 64);
            gemm64<1><<<g, 256>>>(ctx, mix_W1 + (size_t)l * 256 * 128,
                                  mix_b1 + l * 128, h, N, 128, 256);
        }
        // x2 = h mix_W2 + b2 (into xbuf)
        {
            dim3 g(384 / 64, (N + 63) / 64);
            gemm64<0><<<g, 256>>>(h, mix_W2 + (size_t)l * 128 * 384,
                                  mix_b2 + l * 384, xbuf, N, 384, 128);
        }
        epi2_kernel<<<((size_t)N * 128 + 255) / 256, 256>>>(q, mu_o, N);
    }
    // layer parity: l=0 in=muA out=d_out, l=1 in=d_out out=muA, l=2 in=muA out=d_out.
    // Final q and mu land in d_out. (q lives in d_out throughout.)
}

// round 4
// speedup vs baseline: 1.1025x; 1.1025x over previous
#include <cuda_runtime.h>
#include <math.h>

#define F_DIM 128
#define NRBF  20
#define MAXN  10000
#define MAXE  320000
#define NLAYERS 3

// ---------------- device scratch (allocation-free) ----------------
__device__ float g_dir  [MAXE * 3];
__device__ float g_phif [MAXE * NRBF];   // phi * fcut
__device__ float g_fcut [MAXE];
__device__ int   g_rowptr[MAXN + 1];
__device__ float g_x    [MAXN * 384];    // interaction x, reused for mixing x2
__device__ float g_h    [MAXN * 128];
__device__ float g_muA  [MAXN * 384];    // ping-pong partner of d_out mu region
__device__ float g_mumix[MAXN * 768];    // [N,3,256]
__device__ float g_ctx  [MAXN * 256];
__device__ float g_s    [MAXN * 128];

// ---------------- precompute per-edge geometry + RBF ----------------
__global__ void pre_kernel(const float* __restrict__ r_ij, int E) {
    int e = blockIdx.x * blockDim.x + threadIdx.x;
    if (e >= E) return;
    float x = r_ij[e * 3 + 0];
    float y = r_ij[e * 3 + 1];
    float z = r_ij[e * 3 + 2];
    float d = sqrtf(x * x + y * y + z * z);
    float inv = 1.0f / d;
    g_dir[e * 3 + 0] = x * inv;
    g_dir[e * 3 + 1] = y * inv;
    g_dir[e * 3 + 2] = z * inv;
    float fc = (d < 5.0f) ? 0.5f * (cosf(d * 0.62831853071795864769f) + 1.0f) : 0.0f;
    g_fcut[e] = fc;
    const float delta = 5.0f / 19.0f;
    const float coeff = -0.5f / (delta * delta);
#pragma unroll
    for (int r = 0; r < NRBF; r++) {
        float diff = d - delta * (float)r;
        g_phif[e * NRBF + r] = expf(coeff * diff * diff) * fc;
    }
}

// ---------------- segment boundaries (idx_i sorted) ----------------
__global__ void rowptr_kernel(const int* __restrict__ idx_i, int E, int N) {
    int i = blockIdx.x * blockDim.x + threadIdx.x;
    if (i > N) return;
    int lo = 0, hi = E;
    while (lo < hi) {
        int mid = (lo + hi) >> 1;
        if (idx_i[mid] < i) lo = mid + 1; else hi = mid;
    }
    g_rowptr[i] = lo;
}

// ---------------- init q = embedding[an], muA = 0 ----------------
__global__ void init_kernel(const int* __restrict__ an, const float* __restrict__ emb,
                            float* __restrict__ q, int N) {
    int t = blockIdx.x * blockDim.x + threadIdx.x;
    if (t < N * 384) g_muA[t] = 0.0f;
    if (t < N * 128) {
        int n = t >> 7, c = t & 127;
        q[t] = emb[an[n] * 128 + c];
    }
}

// ---------------- double-buffered fp32 GEMM: C = act(A[M,K] @ W[K,N] + bias) --
// BM=BN=64, BK=16, 256 threads, 4x4 per thread. N % 64 == 0, K % 16 == 0.
template <int ACT>   // 0 = none, 1 = silu
__global__ void __launch_bounds__(256)
gemm64(const float* __restrict__ A, const float* __restrict__ W,
       const float* __restrict__ bias, float* __restrict__ C,
       int M, int N, int K) {
    __shared__ float As[2][16][68];
    __shared__ float Bs[2][16][68];
    const int tid  = threadIdx.x;
    const int row0 = blockIdx.y * 64;
    const int col0 = blockIdx.x * 64;
    const int tx = tid & 15, ty = tid >> 4;
    const int ar = tid >> 2;
    const int ak = (tid & 3) << 2;
    const int br = tid >> 4;
    const int bc = (tid & 15) << 2;

    const float* Aptr = A + (size_t)(row0 + ar) * K + ak;
    const bool aval = (row0 + ar) < M;

    float4 aReg = aval ? *(const float4*)Aptr : make_float4(0.f, 0.f, 0.f, 0.f);
    float4 bReg = *(const float4*)&W[(size_t)br * N + col0 + bc];
    As[0][ak + 0][ar] = aReg.x; As[0][ak + 1][ar] = aReg.y;
    As[0][ak + 2][ar] = aReg.z; As[0][ak + 3][ar] = aReg.w;
    *(float4*)&Bs[0][br][bc] = bReg;
    __syncthreads();

    float acc[4][4];
#pragma unroll
    for (int i = 0; i < 4; i++)
#pragma unroll
        for (int j = 0; j < 4; j++) acc[i][j] = 0.0f;

    int buf = 0;
    for (int k0 = 16; k0 < K; k0 += 16) {
        aReg = aval ? *(const float4*)(Aptr + k0) : make_float4(0.f, 0.f, 0.f, 0.f);
        bReg = *(const float4*)&W[(size_t)(k0 + br) * N + col0 + bc];
#pragma unroll
        for (int kk = 0; kk < 16; kk++) {
            float4 a = *(const float4*)&As[buf][kk][ty << 2];
            float4 b = *(const float4*)&Bs[buf][kk][tx << 2];
            acc[0][0] = fmaf(a.x, b.x, acc[0][0]); acc[0][1] = fmaf(a.x, b.y, acc[0][1]);
            acc[0][2] = fmaf(a.x, b.z, acc[0][2]); acc[0][3] = fmaf(a.x, b.w, acc[0][3]);
            acc[1][0] = fmaf(a.y, b.x, acc[1][0]); acc[1][1] = fmaf(a.y, b.y, acc[1][1]);
            acc[1][2] = fmaf(a.y, b.z, acc[1][2]); acc[1][3] = fmaf(a.y, b.w, acc[1][3]);
            acc[2][0] = fmaf(a.z, b.x, acc[2][0]); acc[2][1] = fmaf(a.z, b.y, acc[2][1]);
            acc[2][2] = fmaf(a.z, b.z, acc[2][2]); acc[2][3] = fmaf(a.z, b.w, acc[2][3]);
            acc[3][0] = fmaf(a.w, b.x, acc[3][0]); acc[3][1] = fmaf(a.w, b.y, acc[3][1]);
            acc[3][2] = fmaf(a.w, b.z, acc[3][2]); acc[3][3] = fmaf(a.w, b.w, acc[3][3]);
        }
        buf ^= 1;
        As[buf][ak + 0][ar] = aReg.x; As[buf][ak + 1][ar] = aReg.y;
        As[buf][ak + 2][ar] = aReg.z; As[buf][ak + 3][ar] = aReg.w;
        *(float4*)&Bs[buf][br][bc] = bReg;
        __syncthreads();
    }
#pragma unroll
    for (int kk = 0; kk < 16; kk++) {
        float4 a = *(const float4*)&As[buf][kk][ty << 2];
        float4 b = *(const float4*)&Bs[buf][kk][tx << 2];
        acc[0][0] = fmaf(a.x, b.x, acc[0][0]); acc[0][1] = fmaf(a.x, b.y, acc[0][1]);
        acc[0][2] = fmaf(a.x, b.z, acc[0][2]); acc[0][3] = fmaf(a.x, b.w, acc[0][3]);
        acc[1][0] = fmaf(a.y, b.x, acc[1][0]); acc[1][1] = fmaf(a.y, b.y, acc[1][1]);
        acc[1][2] = fmaf(a.y, b.z, acc[1][2]); acc[1][3] = fmaf(a.y, b.w, acc[1][3]);
        acc[2][0] = fmaf(a.z, b.x, acc[2][0]); acc[2][1] = fmaf(a.z, b.y, acc[2][1]);
        acc[2][2] = fmaf(a.z, b.z, acc[2][2]); acc[2][3] = fmaf(a.z, b.w, acc[2][3]);
        acc[3][0] = fmaf(a.w, b.x, acc[3][0]); acc[3][1] = fmaf(a.w, b.y, acc[3][1]);
        acc[3][2] = fmaf(a.w, b.z, acc[3][2]); acc[3][3] = fmaf(a.w, b.w, acc[3][3]);
    }

#pragma unroll
    for (int i = 0; i < 4; i++) {
        int r = row0 + (ty << 2) + i;
        if (r >= M) continue;
        float4 v;
        float* pv = &v.x;
#pragma unroll
        for (int j = 0; j < 4; j++) {
            float val = acc[i][j];
            if (bias) val += bias[col0 + (tx << 2) + j];
            if (ACT == 1) val = val / (1.0f + expf(-val));
            pv[j] = val;
        }
        *(float4*)&C[(size_t)r * N + col0 + (tx << 2)] = v;
    }
}

// ---------------- edge message + segment-sum kernel (2x unrolled) ----------
// One block (128 threads) per node. Thread c owns feature c.
// Filter weights for this layer held in registers; edge loop unrolled by 2
// with all gathers hoisted so both edges' loads are in flight during the FMAs.
__global__ void __launch_bounds__(128)
edge_kernel(const float* __restrict__ x,
            float* __restrict__ q,
            const float* __restrict__ mu_in,
            float* __restrict__ mu_out,
            const int* __restrict__ idx_j,
            const float* __restrict__ filt_W,
            const float* __restrict__ filt_b,
            int layer, int N) {
    int c = threadIdx.x;   // 0..127
    int layOff = layer * 384;
    float WQc[NRBF], WRc[NRBF], WMc[NRBF];
#pragma unroll
    for (int r = 0; r < NRBF; r++) {
        const float* fw = &filt_W[r * (NLAYERS * 384) + layOff];
        WQc[r] = fw[c];
        WRc[r] = fw[128 + c];
        WMc[r] = fw[256 + c];
    }
    float FBq = filt_b[layOff + c];
    float FBr = filt_b[layOff + 128 + c];
    float FBm = filt_b[layOff + 256 + c];

    int node = blockIdx.x;
    if (node >= N) return;
    int e0 = g_rowptr[node], e1 = g_rowptr[node + 1];
    float accq = 0.f, am0 = 0.f, am1 = 0.f, am2 = 0.f;

    int e = e0;
    for (; e + 2 <= e1; e += 2) {
        // ---- hoisted loads for BOTH edges (max MLP) ----
        int j0 = idx_j[e];
        int j1 = idx_j[e + 1];
        const float* xr0 = &x[(size_t)j0 * 384];
        const float* mj0 = &mu_in[(size_t)j0 * 384];
        const float* xr1 = &x[(size_t)j1 * 384];
        const float* mj1 = &mu_in[(size_t)j1 * 384];
        float x0q = xr0[c], x0R = xr0[128 + c], x0M = xr0[256 + c];
        float m00 = mj0[c], m01 = mj0[128 + c], m02 = mj0[256 + c];
        float x1q = xr1[c], x1R = xr1[128 + c], x1M = xr1[256 + c];
        float m10 = mj1[c], m11 = mj1[128 + c], m12 = mj1[256 + c];
        float d00 = g_dir[e * 3 + 0], d01 = g_dir[e * 3 + 1], d02 = g_dir[e * 3 + 2];
        float d10 = g_dir[e * 3 + 3], d11 = g_dir[e * 3 + 4], d12 = g_dir[e * 3 + 5];
        float fc0 = g_fcut[e], fc1 = g_fcut[e + 1];
        float p0[NRBF], p1[NRBF];
        {
            const float4* pp0 = (const float4*)&g_phif[(size_t)e * NRBF];
#pragma unroll
            for (int v = 0; v < 5; v++) *(float4*)&p0[v * 4] = pp0[v];
#pragma unroll
            for (int v = 0; v < 5; v++) *(float4*)&p1[v * 4] = pp0[v + 5];
        }
        // ---- filters + accumulate, edge 0 ----
        float Wq0 = fc0 * FBq, Wr0 = fc0 * FBr, Wm0 = fc0 * FBm;
#pragma unroll
        for (int r = 0; r < NRBF; r++) {
            Wq0 = fmaf(p0[r], WQc[r], Wq0);
            Wr0 = fmaf(p0[r], WRc[r], Wr0);
            Wm0 = fmaf(p0[r], WMc[r], Wm0);
        }
        accq = fmaf(Wq0, x0q, accq);
        float t0   = Wr0 * x0R;
        float wmx0 = Wm0 * x0M;
        am0 = fmaf(t0, d00, fmaf(wmx0, m00, am0));
        am1 = fmaf(t0, d01, fmaf(wmx0, m01, am1));
        am2 = fmaf(t0, d02, fmaf(wmx0, m02, am2));
        // ---- filters + accumulate, edge 1 ----
        float Wq1 = fc1 * FBq, Wr1 = fc1 * FBr, Wm1 = fc1 * FBm;
#pragma unroll
        for (int r = 0; r < NRBF; r++) {
            Wq1 = fmaf(p1[r], WQc[r], Wq1);
            Wr1 = fmaf(p1[r], WRc[r], Wr1);
            Wm1 = fmaf(p1[r], WMc[r], Wm1);
        }
        accq = fmaf(Wq1, x1q, accq);
        float t1   = Wr1 * x1R;
        float wmx1 = Wm1 * x1M;
        am0 = fmaf(t1, d10, fmaf(wmx1, m10, am0));
        am1 = fmaf(t1, d11, fmaf(wmx1, m11, am1));
        am2 = fmaf(t1, d12, fmaf(wmx1, m12, am2));
    }
    // ---- tail edge ----
    if (e < e1) {
        int j = idx_j[e];
        float p[NRBF];
        const float4* pp = (const float4*)&g_phif[(size_t)e * NRBF];
#pragma unroll
        for (int v = 0; v < 5; v++) *(float4*)&p[v * 4] = pp[v];
        float fc = g_fcut[e];
        float Wq = fc * FBq, Wr = fc * FBr, Wm = fc * FBm;
#pragma unroll
        for (int r = 0; r < NRBF; r++) {
            Wq = fmaf(p[r], WQc[r], Wq);
            Wr = fmaf(p[r], WRc[r], Wr);
            Wm = fmaf(p[r], WMc[r], Wm);
        }
        const float* xr = &x[(size_t)j * 384];
        float xq = xr[c], xR = xr[128 + c], xM = xr[256 + c];
        float d0 = g_dir[e * 3 + 0], d1 = g_dir[e * 3 + 1], d2 = g_dir[e * 3 + 2];
        accq = fmaf(Wq, xq, accq);
        float t   = Wr * xR;
        float wmx = Wm * xM;
        const float* mj = &mu_in[(size_t)j * 384];
        am0 = fmaf(t, d0, fmaf(wmx, mj[c],       am0));
        am1 = fmaf(t, d1, fmaf(wmx, mj[128 + c], am1));
        am2 = fmaf(t, d2, fmaf(wmx, mj[256 + c], am2));
    }

    q[(size_t)node * 128 + c] += accq;
    size_t mb = (size_t)node * 384;
    mu_out[mb + c]       = mu_in[mb + c]       + am0;
    mu_out[mb + 128 + c] = mu_in[mb + 128 + c] + am1;
    mu_out[mb + 256 + c] = mu_in[mb + 256 + c] + am2;
}

// ---------------- mixing stage 1: norms, dot, build ctx ----------------
__global__ void mix1_kernel(const float* __restrict__ q, int N) {
    int t = blockIdx.x * blockDim.x + threadIdx.x;
    if (t >= N * 128) return;
    int n = t >> 7, c = t & 127;
    const float* mm = &g_mumix[(size_t)n * 768];
    float v0 = mm[c],        v1 = mm[256 + c], v2 = mm[512 + c];
    float w0 = mm[128 + c],  w1 = mm[384 + c], w2 = mm[640 + c];
    float vn = sqrtf(v0 * v0 + v1 * v1 + v2 * v2 + 1e-8f);
    g_ctx[(size_t)n * 256 + c]       = q[t];
    g_ctx[(size_t)n * 256 + 128 + c] = vn;
    g_s[t] = v0 * w0 + v1 * w1 + v2 * w2;
}

// ---------------- mixing stage 2: final per-node update ----------------
__global__ void epi2_kernel(float* __restrict__ q, float* __restrict__ mu, int N) {
    int t = blockIdx.x * blockDim.x + threadIdx.x;
    if (t >= N * 128) return;
    int n = t >> 7, c = t & 127;
    const float* xr = &g_x[(size_t)n * 384];
    float dq   = xr[c];
    float dmu  = xr[128 + c];
    float dqmu = xr[256 + c];
    q[t] += dq + dqmu * g_s[t];
    const float* mm = &g_mumix[(size_t)n * 768];
    size_t mb = (size_t)n * 384;
    mu[mb + c]       += dmu * mm[128 + c];
    mu[mb + 128 + c] += dmu * mm[384 + c];
    mu[mb + 256 + c] += dmu * mm[640 + c];
}

// ---------------- host launch ----------------
extern "C" void kernel_launch(void* const* d_in, const int* in_sizes, int n_in,
                              void* d_out, int out_size) {
    const int*   an     = (const int*)  d_in[0];
    const float* r_ij   = (const float*)d_in[1];
    const int*   idx_i  = (const int*)  d_in[2];
    const int*   idx_j  = (const int*)  d_in[3];
    const float* emb    = (const float*)d_in[4];
    const float* filt_W = (const float*)d_in[5];
    const float* filt_b = (const float*)d_in[6];
    const float* int_W1 = (const float*)d_in[7];
    const float* int_b1 = (const float*)d_in[8];
    const float* int_W2 = (const float*)d_in[9];
    const float* int_b2 = (const float*)d_in[10];
    const float* mix_W1 = (const float*)d_in[11];
    const float* mix_b1 = (const float*)d_in[12];
    const float* mix_W2 = (const float*)d_in[13];
    const float* mix_b2 = (const float*)d_in[14];
    const float* mux_W  = (const float*)d_in[15];

    int N = in_sizes[0];
    int E = in_sizes[3];

    float* q      = (float*)d_out;          // [N,128]
    float* mu_out = q + (size_t)N * 128;    // [N,3,128]

    void* pA; cudaGetSymbolAddress(&pA, g_muA);  float* muA  = (float*)pA;
    void* pH; cudaGetSymbolAddress(&pH, g_h);    float* h    = (float*)pH;
    void* pX; cudaGetSymbolAddress(&pX, g_x);    float* xbuf = (float*)pX;
    void* pM; cudaGetSymbolAddress(&pM, g_mumix);float* mumix= (float*)pM;
    void* pC; cudaGetSymbolAddress(&pC, g_ctx);  float* ctx  = (float*)pC;

    // precompute
    pre_kernel   <<<(E + 255) / 256, 256>>>(r_ij, E);
    rowptr_kernel<<<(N + 256) / 256, 256>>>(idx_i, E, N);
    init_kernel  <<<((size_t)N * 384 + 255) / 256, 256>>>(an, emb, q, N);

    for (int l = 0; l < NLAYERS; l++) {
        float* mu_in = (l & 1) ? mu_out : muA;
        float* mu_o  = (l & 1) ? muA    : mu_out;

        // interaction: h = silu(q W1 + b1); x = h W2 + b2
        {
            dim3 g(128 / 64, (N + 63) / 64);
            gemm64<1><<<g, 256>>>(q, int_W1 + (size_t)l * 128 * 128,
                                  int_b1 + l * 128, h, N, 128, 128);
        }
        {
            dim3 g(384 / 64, (N + 63) / 64);
            gemm64<0><<<g, 256>>>(h, int_W2 + (size_t)l * 128 * 384,
                                  int_b2 + l * 384, xbuf, N, 384, 128);
        }
        // edge messages + segment sum (one block per node)
        edge_kernel<<<N, 128>>>(xbuf, q, mu_in, mu_o, idx_j,
                                filt_W, filt_b, l, N);
        // mixing: mumix = mu @ mux_W (no bias), A viewed as [3N,128]
        {
            dim3 g(256 / 64, (3 * N + 63) / 64);
            gemm64<0><<<g, 256>>>(mu_o, mux_W + (size_t)l * 128 * 256,
                                  nullptr, mumix, 3 * N, 256, 128);
        }
        mix1_kernel<<<((size_t)N * 128 + 255) / 256, 256>>>(q, N);
        // h = silu(ctx mix_W1 + b1)
        {
            dim3 g(128 / 64, (N + 63) / 64);
            gemm64<1><<<g, 256>>>(ctx, mix_W1 + (size_t)l * 256 * 128,
                                  mix_b1 + l * 128, h, N, 128, 256);
        }
        // x2 = h mix_W2 + b2 (into xbuf)
        {
            dim3 g(384 / 64, (N + 63) / 64);
            gemm64<0><<<g, 256>>>(h, mix_W2 + (size_t)l * 128 * 384,
                                  mix_b2 + l * 384, xbuf, N, 384, 128);
        }
        epi2_kernel<<<((size_t)N * 128 + 255) / 256, 256>>>(q, mu_o, N);
    }
    // layer parity: l=0 in=muA out=d_out, l=1 in=d_out out=muA, l=2 in=muA out=d_out.
    // Final q and mu land in d_out. (q lives in d_out throughout.)
}

// round 5
// speedup vs baseline: 1.3017x; 1.1806x over previous
#include <cuda_runtime.h>
#include <math.h>

#define F_DIM 128
#define NRBF  20
#define MAXN  10000
#define MAXE  320000
#define NLAYERS 3

// ---------------- device scratch (allocation-free) ----------------
__device__ float g_dir  [MAXE * 3];
__device__ float g_phif [MAXE * NRBF];   // phi * fcut
__device__ float g_fcut [MAXE];
__device__ int   g_rowptr[MAXN + 1];
__device__ float g_x    [MAXN * 384];    // interaction x, reused for mixing x2
__device__ float g_h    [MAXN * 128];
__device__ float g_muA  [MAXN * 384];    // ping-pong partner of d_out mu region
__device__ float g_mumix[MAXN * 768];    // [N,3,256]
__device__ float g_ctx  [MAXN * 256];
__device__ float g_s    [MAXN * 128];

// ---------------- precompute per-edge geometry + RBF ----------------
__global__ void pre_kernel(const float* __restrict__ r_ij, int E) {
    int e = blockIdx.x * blockDim.x + threadIdx.x;
    if (e >= E) return;
    float x = r_ij[e * 3 + 0];
    float y = r_ij[e * 3 + 1];
    float z = r_ij[e * 3 + 2];
    float d = sqrtf(x * x + y * y + z * z);
    float inv = 1.0f / d;
    g_dir[e * 3 + 0] = x * inv;
    g_dir[e * 3 + 1] = y * inv;
    g_dir[e * 3 + 2] = z * inv;
    float fc = (d < 5.0f) ? 0.5f * (cosf(d * 0.62831853071795864769f) + 1.0f) : 0.0f;
    g_fcut[e] = fc;
    const float delta = 5.0f / 19.0f;
    const float coeff = -0.5f / (delta * delta);
#pragma unroll
    for (int r = 0; r < NRBF; r++) {
        float diff = d - delta * (float)r;
        g_phif[e * NRBF + r] = expf(coeff * diff * diff) * fc;
    }
}

// ---------------- segment boundaries (idx_i sorted) ----------------
__global__ void rowptr_kernel(const int* __restrict__ idx_i, int E, int N) {
    int i = blockIdx.x * blockDim.x + threadIdx.x;
    if (i > N) return;
    int lo = 0, hi = E;
    while (lo < hi) {
        int mid = (lo + hi) >> 1;
        if (idx_i[mid] < i) lo = mid + 1; else hi = mid;
    }
    g_rowptr[i] = lo;
}

// ---------------- init q = embedding[an] ----------------
// (g_muA needs no zero-init: every layer's edge kernel fully writes its mu output)
__global__ void init_kernel(const int* __restrict__ an, const float* __restrict__ emb,
                            float* __restrict__ q, int N) {
    int t = blockIdx.x * blockDim.x + threadIdx.x;
    if (t < N * 128) {
        int n = t >> 7, c = t & 127;
        q[t] = emb[an[n] * 128 + c];
    }
}

// ---------------- double-buffered fp32 GEMM: C = act(A[M,K] @ W[K,N] + bias) --
// BM=BN=64, BK=16, 256 threads, 4x4 per thread. N % 64 == 0, K % 16 == 0.
template <int ACT>   // 0 = none, 1 = silu
__global__ void __launch_bounds__(256)
gemm64(const float* __restrict__ A, const float* __restrict__ W,
       const float* __restrict__ bias, float* __restrict__ C,
       int M, int N, int K) {
    __shared__ float As[2][16][68];
    __shared__ float Bs[2][16][68];
    const int tid  = threadIdx.x;
    const int row0 = blockIdx.y * 64;
    const int col0 = blockIdx.x * 64;
    const int tx = tid & 15, ty = tid >> 4;
    const int ar = tid >> 2;
    const int ak = (tid & 3) << 2;
    const int br = tid >> 4;
    const int bc = (tid & 15) << 2;

    const float* Aptr = A + (size_t)(row0 + ar) * K + ak;
    const bool aval = (row0 + ar) < M;

    float4 aReg = aval ? *(const float4*)Aptr : make_float4(0.f, 0.f, 0.f, 0.f);
    float4 bReg = *(const float4*)&W[(size_t)br * N + col0 + bc];
    As[0][ak + 0][ar] = aReg.x; As[0][ak + 1][ar] = aReg.y;
    As[0][ak + 2][ar] = aReg.z; As[0][ak + 3][ar] = aReg.w;
    *(float4*)&Bs[0][br][bc] = bReg;
    __syncthreads();

    float acc[4][4];
#pragma unroll
    for (int i = 0; i < 4; i++)
#pragma unroll
        for (int j = 0; j < 4; j++) acc[i][j] = 0.0f;

    int buf = 0;
    for (int k0 = 16; k0 < K; k0 += 16) {
        aReg = aval ? *(const float4*)(Aptr + k0) : make_float4(0.f, 0.f, 0.f, 0.f);
        bReg = *(const float4*)&W[(size_t)(k0 + br) * N + col0 + bc];
#pragma unroll
        for (int kk = 0; kk < 16; kk++) {
            float4 a = *(const float4*)&As[buf][kk][ty << 2];
            float4 b = *(const float4*)&Bs[buf][kk][tx << 2];
            acc[0][0] = fmaf(a.x, b.x, acc[0][0]); acc[0][1] = fmaf(a.x, b.y, acc[0][1]);
            acc[0][2] = fmaf(a.x, b.z, acc[0][2]); acc[0][3] = fmaf(a.x, b.w, acc[0][3]);
            acc[1][0] = fmaf(a.y, b.x, acc[1][0]); acc[1][1] = fmaf(a.y, b.y, acc[1][1]);
            acc[1][2] = fmaf(a.y, b.z, acc[1][2]); acc[1][3] = fmaf(a.y, b.w, acc[1][3]);
            acc[2][0] = fmaf(a.z, b.x, acc[2][0]); acc[2][1] = fmaf(a.z, b.y, acc[2][1]);
            acc[2][2] = fmaf(a.z, b.z, acc[2][2]); acc[2][3] = fmaf(a.z, b.w, acc[2][3]);
            acc[3][0] = fmaf(a.w, b.x, acc[3][0]); acc[3][1] = fmaf(a.w, b.y, acc[3][1]);
            acc[3][2] = fmaf(a.w, b.z, acc[3][2]); acc[3][3] = fmaf(a.w, b.w, acc[3][3]);
        }
        buf ^= 1;
        As[buf][ak + 0][ar] = aReg.x; As[buf][ak + 1][ar] = aReg.y;
        As[buf][ak + 2][ar] = aReg.z; As[buf][ak + 3][ar] = aReg.w;
        *(float4*)&Bs[buf][br][bc] = bReg;
        __syncthreads();
    }
#pragma unroll
    for (int kk = 0; kk < 16; kk++) {
        float4 a = *(const float4*)&As[buf][kk][ty << 2];
        float4 b = *(const float4*)&Bs[buf][kk][tx << 2];
        acc[0][0] = fmaf(a.x, b.x, acc[0][0]); acc[0][1] = fmaf(a.x, b.y, acc[0][1]);
        acc[0][2] = fmaf(a.x, b.z, acc[0][2]); acc[0][3] = fmaf(a.x, b.w, acc[0][3]);
        acc[1][0] = fmaf(a.y, b.x, acc[1][0]); acc[1][1] = fmaf(a.y, b.y, acc[1][1]);
        acc[1][2] = fmaf(a.y, b.z, acc[1][2]); acc[1][3] = fmaf(a.y, b.w, acc[1][3]);
        acc[2][0] = fmaf(a.z, b.x, acc[2][0]); acc[2][1] = fmaf(a.z, b.y, acc[2][1]);
        acc[2][2] = fmaf(a.z, b.z, acc[2][2]); acc[2][3] = fmaf(a.z, b.w, acc[2][3]);
        acc[3][0] = fmaf(a.w, b.x, acc[3][0]); acc[3][1] = fmaf(a.w, b.y, acc[3][1]);
        acc[3][2] = fmaf(a.w, b.z, acc[3][2]); acc[3][3] = fmaf(a.w, b.w, acc[3][3]);
    }

#pragma unroll
    for (int i = 0; i < 4; i++) {
        int r = row0 + (ty << 2) + i;
        if (r >= M) continue;
        float4 v;
        float* pv = &v.x;
#pragma unroll
        for (int j = 0; j < 4; j++) {
            float val = acc[i][j];
            if (bias) val += bias[col0 + (tx << 2) + j];
            if (ACT == 1) val = val / (1.0f + expf(-val));
            pv[j] = val;
        }
        *(float4*)&C[(size_t)r * N + col0 + (tx << 2)] = v;
    }
}

// ---------------- edge message + segment-sum kernel (general layers) --------
// One block (128 threads) per node. Thread c owns feature c.
// Filter weights for this layer's 3 chunks held in registers (loop-invariant).
__global__ void __launch_bounds__(128)
edge_kernel(const float* __restrict__ x,
            float* __restrict__ q,
            const float* __restrict__ mu_in,
            float* __restrict__ mu_out,
            const int* __restrict__ idx_j,
            const float* __restrict__ filt_W,
            const float* __restrict__ filt_b,
            int layer, int N) {
    int c = threadIdx.x;   // 0..127
    int layOff = layer * 384;
    float WQc[NRBF], WRc[NRBF], WMc[NRBF];
#pragma unroll
    for (int r = 0; r < NRBF; r++) {
        const float* fw = &filt_W[r * (NLAYERS * 384) + layOff];
        WQc[r] = fw[c];
        WRc[r] = fw[128 + c];
        WMc[r] = fw[256 + c];
    }
    float FBq = filt_b[layOff + c];
    float FBr = filt_b[layOff + 128 + c];
    float FBm = filt_b[layOff + 256 + c];

    int node = blockIdx.x;
    if (node >= N) return;
    int e0 = g_rowptr[node], e1 = g_rowptr[node + 1];
    float accq = 0.f, am0 = 0.f, am1 = 0.f, am2 = 0.f;
    for (int e = e0; e < e1; e++) {
        int j = idx_j[e];
        float p[NRBF];
        const float4* pp4 = (const float4*)&g_phif[(size_t)e * NRBF];
#pragma unroll
        for (int v = 0; v < 5; v++) *(float4*)&p[v * 4] = pp4[v];
        float fc = g_fcut[e];
        float Wq = fc * FBq, Wr = fc * FBr, Wm = fc * FBm;
#pragma unroll
        for (int r = 0; r < NRBF; r++) {
            Wq = fmaf(p[r], WQc[r], Wq);
            Wr = fmaf(p[r], WRc[r], Wr);
            Wm = fmaf(p[r], WMc[r], Wm);
        }
        const float* xr = &x[(size_t)j * 384];
        float xq = xr[c], xR = xr[128 + c], xM = xr[256 + c];
        float d0 = g_dir[e * 3 + 0], d1 = g_dir[e * 3 + 1], d2 = g_dir[e * 3 + 2];
        accq = fmaf(Wq, xq, accq);
        float t   = Wr * xR;
        float wmx = Wm * xM;
        const float* mj = &mu_in[(size_t)j * 384];
        am0 = fmaf(t, d0, fmaf(wmx, mj[c],       am0));
        am1 = fmaf(t, d1, fmaf(wmx, mj[128 + c], am1));
        am2 = fmaf(t, d2, fmaf(wmx, mj[256 + c], am2));
    }
    q[(size_t)node * 128 + c] += accq;
    size_t mb = (size_t)node * 384;
    mu_out[mb + c]       = mu_in[mb + c]       + am0;
    mu_out[mb + 128 + c] = mu_in[mb + 128 + c] + am1;
    mu_out[mb + 256 + c] = mu_in[mb + 256 + c] + am2;
}

// ---------------- layer-0 edge kernel: mu_in == 0 everywhere ----------------
// Drops the mu gather, the dmumu term, the whole Wm filter chain, and the xM
// load; writes mu_out directly (no read-accumulate).
__global__ void __launch_bounds__(128)
edge0_kernel(const float* __restrict__ x,
             float* __restrict__ q,
             float* __restrict__ mu_out,
             const int* __restrict__ idx_j,
             const float* __restrict__ filt_W,
             const float* __restrict__ filt_b,
             int N) {
    int c = threadIdx.x;   // 0..127
    float WQc[NRBF], WRc[NRBF];
#pragma unroll
    for (int r = 0; r < NRBF; r++) {
        const float* fw = &filt_W[r * (NLAYERS * 384)];
        WQc[r] = fw[c];
        WRc[r] = fw[128 + c];
    }
    float FBq = filt_b[c];
    float FBr = filt_b[128 + c];

    int node = blockIdx.x;
    if (node >= N) return;
    int e0 = g_rowptr[node], e1 = g_rowptr[node + 1];
    float accq = 0.f, am0 = 0.f, am1 = 0.f, am2 = 0.f;
    for (int e = e0; e < e1; e++) {
        int j = idx_j[e];
        float p[NRBF];
        const float4* pp4 = (const float4*)&g_phif[(size_t)e * NRBF];
#pragma unroll
        for (int v = 0; v < 5; v++) *(float4*)&p[v * 4] = pp4[v];
        float fc = g_fcut[e];
        float Wq = fc * FBq, Wr = fc * FBr;
#pragma unroll
        for (int r = 0; r < NRBF; r++) {
            Wq = fmaf(p[r], WQc[r], Wq);
            Wr = fmaf(p[r], WRc[r], Wr);
        }
        const float* xr = &x[(size_t)j * 384];
        float xq = xr[c], xR = xr[128 + c];
        float d0 = g_dir[e * 3 + 0], d1 = g_dir[e * 3 + 1], d2 = g_dir[e * 3 + 2];
        accq = fmaf(Wq, xq, accq);
        float t = Wr * xR;
        am0 = fmaf(t, d0, am0);
        am1 = fmaf(t, d1, am1);
        am2 = fmaf(t, d2, am2);
    }
    q[(size_t)node * 128 + c] += accq;
    size_t mb = (size_t)node * 384;
    mu_out[mb + c]       = am0;
    mu_out[mb + 128 + c] = am1;
    mu_out[mb + 256 + c] = am2;
}

// ---------------- mixing stage 1: norms, dot, build ctx ----------------
__global__ void mix1_kernel(const float* __restrict__ q, int N) {
    int t = blockIdx.x * blockDim.x + threadIdx.x;
    if (t >= N * 128) return;
    int n = t >> 7, c = t & 127;
    const float* mm = &g_mumix[(size_t)n * 768];
    float v0 = mm[c],        v1 = mm[256 + c], v2 = mm[512 + c];
    float w0 = mm[128 + c],  w1 = mm[384 + c], w2 = mm[640 + c];
    float vn = sqrtf(v0 * v0 + v1 * v1 + v2 * v2 + 1e-8f);
    g_ctx[(size_t)n * 256 + c]       = q[t];
    g_ctx[(size_t)n * 256 + 128 + c] = vn;
    g_s[t] = v0 * w0 + v1 * w1 + v2 * w2;
}

// ---------------- mixing stage 2: final per-node update ----------------
__global__ void epi2_kernel(float* __restrict__ q, float* __restrict__ mu, int N) {
    int t = blockIdx.x * blockDim.x + threadIdx.x;
    if (t >= N * 128) return;
    int n = t >> 7, c = t & 127;
    const float* xr = &g_x[(size_t)n * 384];
    float dq   = xr[c];
    float dmu  = xr[128 + c];
    float dqmu = xr[256 + c];
    q[t] += dq + dqmu * g_s[t];
    const float* mm = &g_mumix[(size_t)n * 768];
    size_t mb = (size_t)n * 384;
    mu[mb + c]       += dmu * mm[128 + c];
    mu[mb + 128 + c] += dmu * mm[384 + c];
    mu[mb + 256 + c] += dmu * mm[640 + c];
}

// ---------------- host launch ----------------
extern "C" void kernel_launch(void* const* d_in, const int* in_sizes, int n_in,
                              void* d_out, int out_size) {
    const int*   an     = (const int*)  d_in[0];
    const float* r_ij   = (const float*)d_in[1];
    const int*   idx_i  = (const int*)  d_in[2];
    const int*   idx_j  = (const int*)  d_in[3];
    const float* emb    = (const float*)d_in[4];
    const float* filt_W = (const float*)d_in[5];
    const float* filt_b = (const float*)d_in[6];
    const float* int_W1 = (const float*)d_in[7];
    const float* int_b1 = (const float*)d_in[8];
    const float* int_W2 = (const float*)d_in[9];
    const float* int_b2 = (const float*)d_in[10];
    const float* mix_W1 = (const float*)d_in[11];
    const float* mix_b1 = (const float*)d_in[12];
    const float* mix_W2 = (const float*)d_in[13];
    const float* mix_b2 = (const float*)d_in[14];
    const float* mux_W  = (const float*)d_in[15];

    int N = in_sizes[0];
    int E = in_sizes[3];

    float* q      = (float*)d_out;          // [N,128]
    float* mu_out = q + (size_t)N * 128;    // [N,3,128]

    void* pA; cudaGetSymbolAddress(&pA, g_muA);  float* muA  = (float*)pA;
    void* pH; cudaGetSymbolAddress(&pH, g_h);    float* h    = (float*)pH;
    void* pX; cudaGetSymbolAddress(&pX, g_x);    float* xbuf = (float*)pX;
    void* pM; cudaGetSymbolAddress(&pM, g_mumix);float* mumix= (float*)pM;
    void* pC; cudaGetSymbolAddress(&pC, g_ctx);  float* ctx  = (float*)pC;

    // precompute
    pre_kernel   <<<(E + 255) / 256, 256>>>(r_ij, E);
    rowptr_kernel<<<(N + 256) / 256, 256>>>(idx_i, E, N);
    init_kernel  <<<((size_t)N * 128 + 255) / 256, 256>>>(an, emb, q, N);

    for (int l = 0; l < NLAYERS; l++) {
        float* mu_in = (l & 1) ? mu_out : muA;
        float* mu_o  = (l & 1) ? muA    : mu_out;

        // interaction: h = silu(q W1 + b1); x = h W2 + b2
        {
            dim3 g(128 / 64, (N + 63) / 64);
            gemm64<1><<<g, 256>>>(q, int_W1 + (size_t)l * 128 * 128,
                                  int_b1 + l * 128, h, N, 128, 128);
        }
        {
            dim3 g(384 / 64, (N + 63) / 64);
            gemm64<0><<<g, 256>>>(h, int_W2 + (size_t)l * 128 * 384,
                                  int_b2 + l * 384, xbuf, N, 384, 128);
        }
        // edge messages + segment sum (one block per node)
        if (l == 0) {
            edge0_kernel<<<N, 128>>>(xbuf, q, mu_o, idx_j, filt_W, filt_b, N);
        } else {
            edge_kernel<<<N, 128>>>(xbuf, q, mu_in, mu_o, idx_j,
                                    filt_W, filt_b, l, N);
        }
        // mixing: mumix = mu @ mux_W (no bias), A viewed as [3N,128]
        {
            dim3 g(256 / 64, (3 * N + 63) / 64);
            gemm64<0><<<g, 256>>>(mu_o, mux_W + (size_t)l * 128 * 256,
                                  nullptr, mumix, 3 * N, 256, 128);
        }
        mix1_kernel<<<((size_t)N * 128 + 255) / 256, 256>>>(q, N);
        // h = silu(ctx mix_W1 + b1)
        {
            dim3 g(128 / 64, (N + 63) / 64);
            gemm64<1><<<g, 256>>>(ctx, mix_W1 + (size_t)l * 256 * 128,
                                  mix_b1 + l * 128, h, N, 128, 256);
        }
        // x2 = h mix_W2 + b2 (into xbuf)
        {
            dim3 g(384 / 64, (N + 63) / 64);
            gemm64<0><<<g, 256>>>(h, mix_W2 + (size_t)l * 128 * 384,
                                  mix_b2 + l * 384, xbuf, N, 384, 128);
        }
        epi2_kernel<<<((size_t)N * 128 + 255) / 256, 256>>>(q, mu_o, N);
    }
    // layer parity: l=0 in=(zero) out=d_out, l=1 in=d_out out=muA, l=2 in=muA out=d_out.
    // Final q and mu land in d_out. (q lives in d_out throughout.)
}

// round 7
// speedup vs baseline: 1.8684x; 1.4354x over previous
#include <cuda_runtime.h>
#include <math.h>

#define NRBF  20
#define MAXN  10000
#define MAXE  320000
#define NLAYERS 3
#define EB 16   // edge batch staged through smem

// ---------------- device scratch (allocation-free) ----------------
__device__ float g_dir  [MAXE * 3];
__device__ float g_phif [MAXE * NRBF];   // phi * fcut
__device__ float g_fcut [MAXE];
__device__ int   g_rowptr[MAXN + 1];
__device__ float g_x    [MAXN * 384];
__device__ float g_h    [MAXN * 128];
__device__ float g_muA  [MAXN * 384];
__device__ float g_mumix[MAXN * 768];
__device__ float g_ctx  [MAXN * 256];
__device__ float g_s    [MAXN * 128];

// ---------------- precompute per-edge geometry + RBF ----------------
__global__ void pre_kernel(const float* __restrict__ r_ij, int E) {
    int e = blockIdx.x * blockDim.x + threadIdx.x;
    if (e >= E) return;
    float x = r_ij[e * 3 + 0];
    float y = r_ij[e * 3 + 1];
    float z = r_ij[e * 3 + 2];
    float d = sqrtf(x * x + y * y + z * z);
    float inv = 1.0f / d;
    g_dir[e * 3 + 0] = x * inv;
    g_dir[e * 3 + 1] = y * inv;
    g_dir[e * 3 + 2] = z * inv;
    float fc = (d < 5.0f) ? 0.5f * (cosf(d * 0.62831853071795864769f) + 1.0f) : 0.0f;
    g_fcut[e] = fc;
    const float delta = 5.0f / 19.0f;
    const float coeff = -0.5f / (delta * delta);
#pragma unroll
    for (int r = 0; r < NRBF; r++) {
        float diff = d - delta * (float)r;
        g_phif[e * NRBF + r] = expf(coeff * diff * diff) * fc;
    }
}

// ---------------- segment boundaries (idx_i sorted) ----------------
__global__ void rowptr_kernel(const int* __restrict__ idx_i, int E, int N) {
    int i = blockIdx.x * blockDim.x + threadIdx.x;
    if (i > N) return;
    int lo = 0, hi = E;
    while (lo < hi) {
        int mid = (lo + hi) >> 1;
        if (idx_i[mid] < i) lo = mid + 1; else hi = mid;
    }
    g_rowptr[i] = lo;
}

// ---------------- init q = embedding[an] ----------------
__global__ void init_kernel(const int* __restrict__ an, const float* __restrict__ emb,
                            float* __restrict__ q, int N) {
    int t = blockIdx.x * blockDim.x + threadIdx.x;
    if (t < N * 128) {
        int n = t >> 7, c = t & 127;
        q[t] = emb[an[n] * 128 + c];
    }
}

// ---------------- double-buffered fp32 GEMM: C = act(A[M,K] @ W[K,N] + bias) --
// BM=BN=64, BK=16, 256 threads, 4x4 per thread. N % 64 == 0, K % 16 == 0.
template <int ACT>   // 0 = none, 1 = silu
__global__ void __launch_bounds__(256)
gemm64(const float* __restrict__ A, const float* __restrict__ W,
       const float* __restrict__ bias, float* __restrict__ C,
       int M, int N, int K) {
    __shared__ float As[2][16][68];
    __shared__ float Bs[2][16][68];
    const int tid  = threadIdx.x;
    const int row0 = blockIdx.y * 64;
    const int col0 = blockIdx.x * 64;
    const int tx = tid & 15, ty = tid >> 4;
    const int ar = tid >> 2;
    const int ak = (tid & 3) << 2;
    const int br = tid >> 4;
    const int bc = (tid & 15) << 2;

    const float* Aptr = A + (size_t)(row0 + ar) * K + ak;
    const bool aval = (row0 + ar) < M;

    float4 aReg = aval ? *(const float4*)Aptr : make_float4(0.f, 0.f, 0.f, 0.f);
    float4 bReg = *(const float4*)&W[(size_t)br * N + col0 + bc];
    As[0][ak + 0][ar] = aReg.x; As[0][ak + 1][ar] = aReg.y;
    As[0][ak + 2][ar] = aReg.z; As[0][ak + 3][ar] = aReg.w;
    *(float4*)&Bs[0][br][bc] = bReg;
    __syncthreads();

    float acc[4][4];
#pragma unroll
    for (int i = 0; i < 4; i++)
#pragma unroll
        for (int j = 0; j < 4; j++) acc[i][j] = 0.0f;

    int buf = 0;
    for (int k0 = 16; k0 < K; k0 += 16) {
        aReg = aval ? *(const float4*)(Aptr + k0) : make_float4(0.f, 0.f, 0.f, 0.f);
        bReg = *(const float4*)&W[(size_t)(k0 + br) * N + col0 + bc];
#pragma unroll
        for (int kk = 0; kk < 16; kk++) {
            float4 a = *(const float4*)&As[buf][kk][ty << 2];
            float4 b = *(const float4*)&Bs[buf][kk][tx << 2];
            acc[0][0] = fmaf(a.x, b.x, acc[0][0]); acc[0][1] = fmaf(a.x, b.y, acc[0][1]);
            acc[0][2] = fmaf(a.x, b.z, acc[0][2]); acc[0][3] = fmaf(a.x, b.w, acc[0][3]);
            acc[1][0] = fmaf(a.y, b.x, acc[1][0]); acc[1][1] = fmaf(a.y, b.y, acc[1][1]);
            acc[1][2] = fmaf(a.y, b.z, acc[1][2]); acc[1][3] = fmaf(a.y, b.w, acc[1][3]);
            acc[2][0] = fmaf(a.z, b.x, acc[2][0]); acc[2][1] = fmaf(a.z, b.y, acc[2][1]);
            acc[2][2] = fmaf(a.z, b.z, acc[2][2]); acc[2][3] = fmaf(a.z, b.w, acc[2][3]);
            acc[3][0] = fmaf(a.w, b.x, acc[3][0]); acc[3][1] = fmaf(a.w, b.y, acc[3][1]);
            acc[3][2] = fmaf(a.w, b.z, acc[3][2]); acc[3][3] = fmaf(a.w, b.w, acc[3][3]);
        }
        buf ^= 1;
        As[buf][ak + 0][ar] = aReg.x; As[buf][ak + 1][ar] = aReg.y;
        As[buf][ak + 2][ar] = aReg.z; As[buf][ak + 3][ar] = aReg.w;
        *(float4*)&Bs[buf][br][bc] = bReg;
        __syncthreads();
    }
#pragma unroll
    for (int kk = 0; kk < 16; kk++) {
        float4 a = *(const float4*)&As[buf][kk][ty << 2];
        float4 b = *(const float4*)&Bs[buf][kk][tx << 2];
        acc[0][0] = fmaf(a.x, b.x, acc[0][0]); acc[0][1] = fmaf(a.x, b.y, acc[0][1]);
        acc[0][2] = fmaf(a.x, b.z, acc[0][2]); acc[0][3] = fmaf(a.x, b.w, acc[0][3]);
        acc[1][0] = fmaf(a.y, b.x, acc[1][0]); acc[1][1] = fmaf(a.y, b.y, acc[1][1]);
        acc[1][2] = fmaf(a.y, b.z, acc[1][2]); acc[1][3] = fmaf(a.y, b.w, acc[1][3]);
        acc[2][0] = fmaf(a.z, b.x, acc[2][0]); acc[2][1] = fmaf(a.z, b.y, acc[2][1]);
        acc[2][2] = fmaf(a.z, b.z, acc[2][2]); acc[2][3] = fmaf(a.z, b.w, acc[2][3]);
        acc[3][0] = fmaf(a.w, b.x, acc[3][0]); acc[3][1] = fmaf(a.w, b.y, acc[3][1]);
        acc[3][2] = fmaf(a.w, b.z, acc[3][2]); acc[3][3] = fmaf(a.w, b.w, acc[3][3]);
    }

#pragma unroll
    for (int i = 0; i < 4; i++) {
        int r = row0 + (ty << 2) + i;
        if (r >= M) continue;
        float4 v;
        float* pv = &v.x;
#pragma unroll
        for (int j = 0; j < 4; j++) {
            float val = acc[i][j];
            if (bias) val += bias[col0 + (tx << 2) + j];
            if (ACT == 1) val = val / (1.0f + expf(-val));
            pv[j] = val;
        }
        *(float4*)&C[(size_t)r * N + col0 + (tx << 2)] = v;
    }
}

// ---------------- edge message + segment-sum kernel (general layers) --------
// One block (128 threads) per node. Thread c owns feature c.
// Edges staged through smem in batches of EB: phif/dir/fcut/idx loaded once
// per block (coalesced), consumed via broadcast LDS instead of redundant LDG.
__global__ void __launch_bounds__(128)
edge_kernel(const float* __restrict__ x,
            float* __restrict__ q,
            const float* __restrict__ mu_in,
            float* __restrict__ mu_out,
            const int* __restrict__ idx_j,
            const float* __restrict__ filt_W,
            const float* __restrict__ filt_b,
            int layer, int N) {
    __shared__ __align__(16) float s_phif[EB * NRBF];
    __shared__ float s_dir[EB * 3];
    __shared__ float s_fcut[EB];
    __shared__ int   s_idx[EB];

    int c = threadIdx.x;   // 0..127
    int layOff = layer * 384;
    float WQc[NRBF], WRc[NRBF], WMc[NRBF];
#pragma unroll
    for (int r = 0; r < NRBF; r++) {
        const float* fw = &filt_W[r * (NLAYERS * 384) + layOff];
        WQc[r] = fw[c];
        WRc[r] = fw[128 + c];
        WMc[r] = fw[256 + c];
    }
    float FBq = filt_b[layOff + c];
    float FBr = filt_b[layOff + 128 + c];
    float FBm = filt_b[layOff + 256 + c];

    int node = blockIdx.x;
    if (node >= N) return;
    int e0 = g_rowptr[node], e1 = g_rowptr[node + 1];
    float accq = 0.f, am0 = 0.f, am1 = 0.f, am2 = 0.f;

    for (int eb = e0; eb < e1; eb += EB) {
        int cnt = min(EB, e1 - eb);
        __syncthreads();   // previous batch fully consumed
        // ---- cooperative stage (edges are contiguous in memory) ----
        if (c < cnt * 5)                     // phif: cnt*5 float4, 16B aligned
            *(float4*)&s_phif[c << 2] = *(const float4*)&g_phif[(size_t)eb * NRBF + (c << 2)];
        int t = c - 80;
        if (t >= 0 && t < cnt * 3)           // dir: cnt*3 scalars
            s_dir[t] = g_dir[(size_t)eb * 3 + t];
        if (c < cnt) s_fcut[c] = g_fcut[eb + c];
        int u = c - 16;
        if (u >= 0 && u < cnt) s_idx[u] = idx_j[eb + u];
        __syncthreads();

        for (int i = 0; i < cnt; i++) {
            // gathers first (long-latency, per-thread)
            int j = s_idx[i];
            const float* xr = &x[(size_t)j * 384];
            const float* mj = &mu_in[(size_t)j * 384];
            float xq = xr[c], xR = xr[128 + c], xM = xr[256 + c];
            float m0 = mj[c], m1 = mj[128 + c], m2 = mj[256 + c];
            // broadcast LDS (conflict-free)
            float p[NRBF];
#pragma unroll
            for (int v = 0; v < 5; v++)
                *(float4*)&p[v * 4] = *(const float4*)&s_phif[i * NRBF + v * 4];
            float fc = s_fcut[i];
            float d0 = s_dir[i * 3 + 0], d1 = s_dir[i * 3 + 1], d2 = s_dir[i * 3 + 2];
            float Wq = fc * FBq, Wr = fc * FBr, Wm = fc * FBm;
#pragma unroll
            for (int r = 0; r < NRBF; r++) {
                Wq = fmaf(p[r], WQc[r], Wq);
                Wr = fmaf(p[r], WRc[r], Wr);
                Wm = fmaf(p[r], WMc[r], Wm);
            }
            accq = fmaf(Wq, xq, accq);
            float tt  = Wr * xR;
            float wmx = Wm * xM;
            am0 = fmaf(tt, d0, fmaf(wmx, m0, am0));
            am1 = fmaf(tt, d1, fmaf(wmx, m1, am1));
            am2 = fmaf(tt, d2, fmaf(wmx, m2, am2));
        }
    }
    q[(size_t)node * 128 + c] += accq;
    size_t mb = (size_t)node * 384;
    mu_out[mb + c]       = mu_in[mb + c]       + am0;
    mu_out[mb + 128 + c] = mu_in[mb + 128 + c] + am1;
    mu_out[mb + 256 + c] = mu_in[mb + 256 + c] + am2;
}

// ---------------- layer-0 edge kernel: mu_in == 0 everywhere ----------------
__global__ void __launch_bounds__(128)
edge0_kernel(const float* __restrict__ x,
             float* __restrict__ q,
             float* __restrict__ mu_out,
             const int* __restrict__ idx_j,
             const float* __restrict__ filt_W,
             const float* __restrict__ filt_b,
             int N) {
    __shared__ __align__(16) float s_phif[EB * NRBF];
    __shared__ float s_dir[EB * 3];
    __shared__ float s_fcut[EB];
    __shared__ int   s_idx[EB];

    int c = threadIdx.x;
    float WQc[NRBF], WRc[NRBF];
#pragma unroll
    for (int r = 0; r < NRBF; r++) {
        const float* fw = &filt_W[r * (NLAYERS * 384)];
        WQc[r] = fw[c];
        WRc[r] = fw[128 + c];
    }
    float FBq = filt_b[c];
    float FBr = filt_b[128 + c];

    int node = blockIdx.x;
    if (node >= N) return;
    int e0 = g_rowptr[node], e1 = g_rowptr[node + 1];
    float accq = 0.f, am0 = 0.f, am1 = 0.f, am2 = 0.f;

    for (int eb = e0; eb < e1; eb += EB) {
        int cnt = min(EB, e1 - eb);
        __syncthreads();
        if (c < cnt * 5)
            *(float4*)&s_phif[c << 2] = *(const float4*)&g_phif[(size_t)eb * NRBF + (c << 2)];
        int t = c - 80;
        if (t >= 0 && t < cnt * 3)
            s_dir[t] = g_dir[(size_t)eb * 3 + t];
        if (c < cnt) s_fcut[c] = g_fcut[eb + c];
        int u = c - 16;
        if (u >= 0 && u < cnt) s_idx[u] = idx_j[eb + u];
        __syncthreads();

        for (int i = 0; i < cnt; i++) {
            int j = s_idx[i];
            const float* xr = &x[(size_t)j * 384];
            float xq = xr[c], xR = xr[128 + c];
            float p[NRBF];
#pragma unroll
            for (int v = 0; v < 5; v++)
                *(float4*)&p[v * 4] = *(const float4*)&s_phif[i * NRBF + v * 4];
            float fc = s_fcut[i];
            float d0 = s_dir[i * 3 + 0], d1 = s_dir[i * 3 + 1], d2 = s_dir[i * 3 + 2];
            float Wq = fc * FBq, Wr = fc * FBr;
#pragma unroll
            for (int r = 0; r < NRBF; r++) {
                Wq = fmaf(p[r], WQc[r], Wq);
                Wr = fmaf(p[r], WRc[r], Wr);
            }
            accq = fmaf(Wq, xq, accq);
            float tt = Wr * xR;
            am0 = fmaf(tt, d0, am0);
            am1 = fmaf(tt, d1, am1);
            am2 = fmaf(tt, d2, am2);
        }
    }
    q[(size_t)node * 128 + c] += accq;
    size_t mb = (size_t)node * 384;
    mu_out[mb + c]       = am0;
    mu_out[mb + 128 + c] = am1;
    mu_out[mb + 256 + c] = am2;
}

// ---------------- mixing stage 1: norms, dot, build ctx ----------------
__global__ void mix1_kernel(const float* __restrict__ q, int N) {
    int t = blockIdx.x * blockDim.x + threadIdx.x;
    if (t >= N * 128) return;
    int n = t >> 7, c = t & 127;
    const float* mm = &g_mumix[(size_t)n * 768];
    float v0 = mm[c],        v1 = mm[256 + c], v2 = mm[512 + c];
    float w0 = mm[128 + c],  w1 = mm[384 + c], w2 = mm[640 + c];
    float vn = sqrtf(v0 * v0 + v1 * v1 + v2 * v2 + 1e-8f);
    g_ctx[(size_t)n * 256 + c]       = q[t];
    g_ctx[(size_t)n * 256 + 128 + c] = vn;
    g_s[t] = v0 * w0 + v1 * w1 + v2 * w2;
}

// ---------------- mixing stage 2: final per-node update ----------------
__global__ void epi2_kernel(float* __restrict__ q, float* __restrict__ mu, int N) {
    int t = blockIdx.x * blockDim.x + threadIdx.x;
    if (t >= N * 128) return;
    int n = t >> 7, c = t & 127;
    const float* xr = &g_x[(size_t)n * 384];
    float dq   = xr[c];
    float dmu  = xr[128 + c];
    float dqmu = xr[256 + c];
    q[t] += dq + dqmu * g_s[t];
    const float* mm = &g_mumix[(size_t)n * 768];
    size_t mb = (size_t)n * 384;
    mu[mb + c]       += dmu * mm[128 + c];
    mu[mb + 128 + c] += dmu * mm[384 + c];
    mu[mb + 256 + c] += dmu * mm[640 + c];
}

// ---------------- host launch ----------------
extern "C" void kernel_launch(void* const* d_in, const int* in_sizes, int n_in,
                              void* d_out, int out_size) {
    const int*   an     = (const int*)  d_in[0];
    const float* r_ij   = (const float*)d_in[1];
    const int*   idx_i  = (const int*)  d_in[2];
    const int*   idx_j  = (const int*)  d_in[3];
    const float* emb    = (const float*)d_in[4];
    const float* filt_W = (const float*)d_in[5];
    const float* filt_b = (const float*)d_in[6];
    const float* int_W1 = (const float*)d_in[7];
    const float* int_b1 = (const float*)d_in[8];
    const float* int_W2 = (const float*)d_in[9];
    const float* int_b2 = (const float*)d_in[10];
    const float* mix_W1 = (const float*)d_in[11];
    const float* mix_b1 = (const float*)d_in[12];
    const float* mix_W2 = (const float*)d_in[13];
    const float* mix_b2 = (const float*)d_in[14];
    const float* mux_W  = (const float*)d_in[15];

    int N = in_sizes[0];
    int E = in_sizes[3];

    float* q      = (float*)d_out;          // [N,128]
    float* mu_out = q + (size_t)N * 128;    // [N,3,128]

    void* pA; cudaGetSymbolAddress(&pA, g_muA);  float* muA  = (float*)pA;
    void* pH; cudaGetSymbolAddress(&pH, g_h);    float* h    = (float*)pH;
    void* pX; cudaGetSymbolAddress(&pX, g_x);    float* xbuf = (float*)pX;
    void* pM; cudaGetSymbolAddress(&pM, g_mumix);float* mumix= (float*)pM;
    void* pC; cudaGetSymbolAddress(&pC, g_ctx);  float* ctx  = (float*)pC;

    // precompute
    pre_kernel   <<<(E + 255) / 256, 256>>>(r_ij, E);
    rowptr_kernel<<<(N + 256) / 256, 256>>>(idx_i, E, N);
    init_kernel  <<<((size_t)N * 128 + 255) / 256, 256>>>(an, emb, q, N);

    for (int l = 0; l < NLAYERS; l++) {
        float* mu_in = (l & 1) ? mu_out : muA;
        float* mu_o  = (l & 1) ? muA    : mu_out;

        // interaction: h = silu(q W1 + b1); x = h W2 + b2
        {
            dim3 g(128 / 64, (N + 63) / 64);
            gemm64<1><<<g, 256>>>(q, int_W1 + (size_t)l * 128 * 128,
                                  int_b1 + l * 128, h, N, 128, 128);
        }
        {
            dim3 g(384 / 64, (N + 63) / 64);
            gemm64<0><<<g, 256>>>(h, int_W2 + (size_t)l * 128 * 384,
                                  int_b2 + l * 384, xbuf, N, 384, 128);
        }
        // edge messages + segment sum (one block per node)
        if (l == 0) {
            edge0_kernel<<<N, 128>>>(xbuf, q, mu_o, idx_j, filt_W, filt_b, N);
        } else {
            edge_kernel<<<N, 128>>>(xbuf, q, mu_in, mu_o, idx_j,
                                    filt_W, filt_b, l, N);
        }
        // mixing: mumix = mu @ mux_W (no bias), A viewed as [3N,128]
        {
            dim3 g(256 / 64, (3 * N + 63) / 64);
            gemm64<0><<<g, 256>>>(mu_o, mux_W + (size_t)l * 128 * 256,
                                  nullptr, mumix, 3 * N, 256, 128);
        }
        mix1_kernel<<<((size_t)N * 128 + 255) / 256, 256>>>(q, N);
        // h = silu(ctx mix_W1 + b1)
        {
            dim3 g(128 / 64, (N + 63) / 64);
            gemm64<1><<<g, 256>>>(ctx, mix_W1 + (size_t)l * 256 * 128,
                                  mix_b1 + l * 128, h, N, 128, 256);
        }
        // x2 = h mix_W2 + b2 (into xbuf)
        {
            dim3 g(384 / 64, (N + 63) / 64);
            gemm64<0><<<g, 256>>>(h, mix_W2 + (size_t)l * 128 * 384,
                                  mix_b2 + l * 384, xbuf, N, 384, 128);
        }
        epi2_kernel<<<((size_t)N * 128 + 255) / 256, 256>>>(q, mu_o, N);
    }
    // layer parity: l=0 in=(zero) out=d_out, l=1 in=d_out out=muA, l=2 in=muA out=d_out.
    // Final q and mu land in d_out. (q lives in d_out throughout.)
}

// round 8
// speedup vs baseline: 1.9295x; 1.0327x over previous
#include <cuda_runtime.h>
#include <math.h>

#define NRBF  20
#define MAXN  10000
#define MAXE  320000
#define NLAYERS 3
#define EB 16   // edge batch staged through smem

// ---------------- device scratch (allocation-free) ----------------
__device__ float g_dir  [MAXE * 3];
__device__ float g_phif [MAXE * NRBF];   // phi * fcut
__device__ float g_fcut [MAXE];
__device__ int   g_rowptr[MAXN + 1];
__device__ float g_x    [MAXN * 384];
__device__ float g_h    [MAXN * 128];
__device__ float g_muA  [MAXN * 384];
__device__ float g_mumix[MAXN * 768];
__device__ float g_ctx  [MAXN * 256];
__device__ float g_s    [MAXN * 128];

// ---------------- precompute per-edge geometry + RBF ----------------
__global__ void pre_kernel(const float* __restrict__ r_ij, int E) {
    int e = blockIdx.x * blockDim.x + threadIdx.x;
    if (e >= E) return;
    float x = r_ij[e * 3 + 0];
    float y = r_ij[e * 3 + 1];
    float z = r_ij[e * 3 + 2];
    float d = sqrtf(x * x + y * y + z * z);
    float inv = 1.0f / d;
    g_dir[e * 3 + 0] = x * inv;
    g_dir[e * 3 + 1] = y * inv;
    g_dir[e * 3 + 2] = z * inv;
    float fc = (d < 5.0f) ? 0.5f * (cosf(d * 0.62831853071795864769f) + 1.0f) : 0.0f;
    g_fcut[e] = fc;
    const float delta = 5.0f / 19.0f;
    const float coeff = -0.5f / (delta * delta);
#pragma unroll
    for (int r = 0; r < NRBF; r++) {
        float diff = d - delta * (float)r;
        g_phif[e * NRBF + r] = expf(coeff * diff * diff) * fc;
    }
}

// ---------------- segment boundaries (idx_i sorted) ----------------
__global__ void rowptr_kernel(const int* __restrict__ idx_i, int E, int N) {
    int i = blockIdx.x * blockDim.x + threadIdx.x;
    if (i > N) return;
    int lo = 0, hi = E;
    while (lo < hi) {
        int mid = (lo + hi) >> 1;
        if (idx_i[mid] < i) lo = mid + 1; else hi = mid;
    }
    g_rowptr[i] = lo;
}

// ---------------- init q = embedding[an] ----------------
__global__ void init_kernel(const int* __restrict__ an, const float* __restrict__ emb,
                            float* __restrict__ q, int N) {
    int t = blockIdx.x * blockDim.x + threadIdx.x;
    if (t < N * 128) {
        int n = t >> 7, c = t & 127;
        q[t] = emb[an[n] * 128 + c];
    }
}

// ---------------- double-buffered fp32 GEMM: C = act(A[M,K] @ W[K,N] + bias) --
// BM=BN=64, BK=32, 256 threads, 4x4 per thread. N % 64 == 0, K % 32 == 0.
template <int ACT>   // 0 = none, 1 = silu
__global__ void __launch_bounds__(256)
gemm64(const float* __restrict__ A, const float* __restrict__ W,
       const float* __restrict__ bias, float* __restrict__ C,
       int M, int N, int K) {
    __shared__ float As[2][32][68];   // [buf][k][m]
    __shared__ float Bs[2][32][68];   // [buf][k][n]
    const int tid  = threadIdx.x;
    const int row0 = blockIdx.y * 64;
    const int col0 = blockIdx.x * 64;
    const int tx = tid & 15, ty = tid >> 4;

    // A tile: 64 rows x 32 k = 512 float4 slots (2 per thread)
    // slot s: ar = s>>3 (0..63), ak = (s&7)*4
    // B tile: 32 k x 64 cols = 512 float4 slots (2 per thread)
    // slot s: br = s>>4 (0..31), bc = (s&15)*4
    int ar0 = tid >> 3,          ak0 = (tid & 7) << 2;
    int ar1 = (tid + 256) >> 3,  ak1 = ak0;   // (s&7) identical for s and s+256
    int br0 = tid >> 4,          bc0 = (tid & 15) << 2;
    int br1 = (tid + 256) >> 4,  bc1 = bc0;

    const bool av0 = (row0 + ar0) < M;
    const bool av1 = (row0 + ar1) < M;
    const float* Ap0 = A + (size_t)(row0 + ar0) * K + ak0;
    const float* Ap1 = A + (size_t)(row0 + ar1) * K + ak1;
    const float* Wp0 = W + (size_t)br0 * N + col0 + bc0;
    const float* Wp1 = W + (size_t)br1 * N + col0 + bc1;

    float4 a0 = av0 ? *(const float4*)Ap0 : make_float4(0.f, 0.f, 0.f, 0.f);
    float4 a1 = av1 ? *(const float4*)Ap1 : make_float4(0.f, 0.f, 0.f, 0.f);
    float4 b0 = *(const float4*)Wp0;
    float4 b1 = *(const float4*)Wp1;
    As[0][ak0 + 0][ar0] = a0.x; As[0][ak0 + 1][ar0] = a0.y;
    As[0][ak0 + 2][ar0] = a0.z; As[0][ak0 + 3][ar0] = a0.w;
    As[0][ak1 + 0][ar1] = a1.x; As[0][ak1 + 1][ar1] = a1.y;
    As[0][ak1 + 2][ar1] = a1.z; As[0][ak1 + 3][ar1] = a1.w;
    *(float4*)&Bs[0][br0][bc0] = b0;
    *(float4*)&Bs[0][br1][bc1] = b1;
    __syncthreads();

    float acc[4][4];
#pragma unroll
    for (int i = 0; i < 4; i++)
#pragma unroll
        for (int j = 0; j < 4; j++) acc[i][j] = 0.0f;

    int buf = 0;
    for (int k0 = 32; k0 < K; k0 += 32) {
        // prefetch next k-tile into registers
        a0 = av0 ? *(const float4*)(Ap0 + k0) : make_float4(0.f, 0.f, 0.f, 0.f);
        a1 = av1 ? *(const float4*)(Ap1 + k0) : make_float4(0.f, 0.f, 0.f, 0.f);
        b0 = *(const float4*)(Wp0 + (size_t)k0 * N);
        b1 = *(const float4*)(Wp1 + (size_t)k0 * N);
#pragma unroll
        for (int kk = 0; kk < 32; kk++) {
            float4 a = *(const float4*)&As[buf][kk][ty << 2];
            float4 b = *(const float4*)&Bs[buf][kk][tx << 2];
            acc[0][0] = fmaf(a.x, b.x, acc[0][0]); acc[0][1] = fmaf(a.x, b.y, acc[0][1]);
            acc[0][2] = fmaf(a.x, b.z, acc[0][2]); acc[0][3] = fmaf(a.x, b.w, acc[0][3]);
            acc[1][0] = fmaf(a.y, b.x, acc[1][0]); acc[1][1] = fmaf(a.y, b.y, acc[1][1]);
            acc[1][2] = fmaf(a.y, b.z, acc[1][2]); acc[1][3] = fmaf(a.y, b.w, acc[1][3]);
            acc[2][0] = fmaf(a.z, b.x, acc[2][0]); acc[2][1] = fmaf(a.z, b.y, acc[2][1]);
            acc[2][2] = fmaf(a.z, b.z, acc[2][2]); acc[2][3] = fmaf(a.z, b.w, acc[2][3]);
            acc[3][0] = fmaf(a.w, b.x, acc[3][0]); acc[3][1] = fmaf(a.w, b.y, acc[3][1]);
            acc[3][2] = fmaf(a.w, b.z, acc[3][2]); acc[3][3] = fmaf(a.w, b.w, acc[3][3]);
        }
        buf ^= 1;
        As[buf][ak0 + 0][ar0] = a0.x; As[buf][ak0 + 1][ar0] = a0.y;
        As[buf][ak0 + 2][ar0] = a0.z; As[buf][ak0 + 3][ar0] = a0.w;
        As[buf][ak1 + 0][ar1] = a1.x; As[buf][ak1 + 1][ar1] = a1.y;
        As[buf][ak1 + 2][ar1] = a1.z; As[buf][ak1 + 3][ar1] = a1.w;
        *(float4*)&Bs[buf][br0][bc0] = b0;
        *(float4*)&Bs[buf][br1][bc1] = b1;
        __syncthreads();
    }
#pragma unroll
    for (int kk = 0; kk < 32; kk++) {
        float4 a = *(const float4*)&As[buf][kk][ty << 2];
        float4 b = *(const float4*)&Bs[buf][kk][tx << 2];
        acc[0][0] = fmaf(a.x, b.x, acc[0][0]); acc[0][1] = fmaf(a.x, b.y, acc[0][1]);
        acc[0][2] = fmaf(a.x, b.z, acc[0][2]); acc[0][3] = fmaf(a.x, b.w, acc[0][3]);
        acc[1][0] = fmaf(a.y, b.x, acc[1][0]); acc[1][1] = fmaf(a.y, b.y, acc[1][1]);
        acc[1][2] = fmaf(a.y, b.z, acc[1][2]); acc[1][3] = fmaf(a.y, b.w, acc[1][3]);
        acc[2][0] = fmaf(a.z, b.x, acc[2][0]); acc[2][1] = fmaf(a.z, b.y, acc[2][1]);
        acc[2][2] = fmaf(a.z, b.z, acc[2][2]); acc[2][3] = fmaf(a.z, b.w, acc[2][3]);
        acc[3][0] = fmaf(a.w, b.x, acc[3][0]); acc[3][1] = fmaf(a.w, b.y, acc[3][1]);
        acc[3][2] = fmaf(a.w, b.z, acc[3][2]); acc[3][3] = fmaf(a.w, b.w, acc[3][3]);
    }

    // epilogue (bias hoisted)
    float bj[4] = {0.f, 0.f, 0.f, 0.f};
    if (bias) {
#pragma unroll
        for (int j = 0; j < 4; j++) bj[j] = bias[col0 + (tx << 2) + j];
    }
#pragma unroll
    for (int i = 0; i < 4; i++) {
        int r = row0 + (ty << 2) + i;
        if (r >= M) continue;
        float4 v;
        float* pv = &v.x;
#pragma unroll
        for (int j = 0; j < 4; j++) {
            float val = acc[i][j] + bj[j];
            if (ACT == 1) val = val / (1.0f + expf(-val));
            pv[j] = val;
        }
        *(float4*)&C[(size_t)r * N + col0 + (tx << 2)] = v;
    }
}

// ---------------- edge message + segment-sum kernel (general layers) --------
// One block (128 threads) per node. Thread c owns feature c.
// Edges staged through smem in batches of EB: phif/dir/fcut/idx loaded once
// per block (coalesced), consumed via broadcast LDS instead of redundant LDG.
__global__ void __launch_bounds__(128)
edge_kernel(const float* __restrict__ x,
            float* __restrict__ q,
            const float* __restrict__ mu_in,
            float* __restrict__ mu_out,
            const int* __restrict__ idx_j,
            const float* __restrict__ filt_W,
            const float* __restrict__ filt_b,
            int layer, int N) {
    __shared__ __align__(16) float s_phif[EB * NRBF];
    __shared__ float s_dir[EB * 3];
    __shared__ float s_fcut[EB];
    __shared__ int   s_idx[EB];

    int c = threadIdx.x;   // 0..127
    int layOff = layer * 384;
    float WQc[NRBF], WRc[NRBF], WMc[NRBF];
#pragma unroll
    for (int r = 0; r < NRBF; r++) {
        const float* fw = &filt_W[r * (NLAYERS * 384) + layOff];
        WQc[r] = fw[c];
        WRc[r] = fw[128 + c];
        WMc[r] = fw[256 + c];
    }
    float FBq = filt_b[layOff + c];
    float FBr = filt_b[layOff + 128 + c];
    float FBm = filt_b[layOff + 256 + c];

    int node = blockIdx.x;
    if (node >= N) return;
    int e0 = g_rowptr[node], e1 = g_rowptr[node + 1];
    float accq = 0.f, am0 = 0.f, am1 = 0.f, am2 = 0.f;

    for (int eb = e0; eb < e1; eb += EB) {
        int cnt = min(EB, e1 - eb);
        __syncthreads();   // previous batch fully consumed
        if (c < cnt * 5)
            *(float4*)&s_phif[c << 2] = *(const float4*)&g_phif[(size_t)eb * NRBF + (c << 2)];
        int t = c - 80;
        if (t >= 0 && t < cnt * 3)
            s_dir[t] = g_dir[(size_t)eb * 3 + t];
        if (c < cnt) s_fcut[c] = g_fcut[eb + c];
        int u = c - 16;
        if (u >= 0 && u < cnt) s_idx[u] = idx_j[eb + u];
        __syncthreads();

        for (int i = 0; i < cnt; i++) {
            int j = s_idx[i];
            const float* xr = &x[(size_t)j * 384];
            const float* mj = &mu_in[(size_t)j * 384];
            float xq = xr[c], xR = xr[128 + c], xM = xr[256 + c];
            float m0 = mj[c], m1 = mj[128 + c], m2 = mj[256 + c];
            float p[NRBF];
#pragma unroll
            for (int v = 0; v < 5; v++)
                *(float4*)&p[v * 4] = *(const float4*)&s_phif[i * NRBF + v * 4];
            float fc = s_fcut[i];
            float d0 = s_dir[i * 3 + 0], d1 = s_dir[i * 3 + 1], d2 = s_dir[i * 3 + 2];
            float Wq = fc * FBq, Wr = fc * FBr, Wm = fc * FBm;
#pragma unroll
            for (int r = 0; r < NRBF; r++) {
                Wq = fmaf(p[r], WQc[r], Wq);
                Wr = fmaf(p[r], WRc[r], Wr);
                Wm = fmaf(p[r], WMc[r], Wm);
            }
            accq = fmaf(Wq, xq, accq);
            float tt  = Wr * xR;
            float wmx = Wm * xM;
            am0 = fmaf(tt, d0, fmaf(wmx, m0, am0));
            am1 = fmaf(tt, d1, fmaf(wmx, m1, am1));
            am2 = fmaf(tt, d2, fmaf(wmx, m2, am2));
        }
    }
    q[(size_t)node * 128 + c] += accq;
    size_t mb = (size_t)node * 384;
    mu_out[mb + c]       = mu_in[mb + c]       + am0;
    mu_out[mb + 128 + c] = mu_in[mb + 128 + c] + am1;
    mu_out[mb + 256 + c] = mu_in[mb + 256 + c] + am2;
}

// ---------------- layer-0 edge kernel: mu_in == 0 everywhere ----------------
__global__ void __launch_bounds__(128)
edge0_kernel(const float* __restrict__ x,
             float* __restrict__ q,
             float* __restrict__ mu_out,
             const int* __restrict__ idx_j,
             const float* __restrict__ filt_W,
             const float* __restrict__ filt_b,
             int N) {
    __shared__ __align__(16) float s_phif[EB * NRBF];
    __shared__ float s_dir[EB * 3];
    __shared__ float s_fcut[EB];
    __shared__ int   s_idx[EB];

    int c = threadIdx.x;
    float WQc[NRBF], WRc[NRBF];
#pragma unroll
    for (int r = 0; r < NRBF; r++) {
        const float* fw = &filt_W[r * (NLAYERS * 384)];
        WQc[r] = fw[c];
        WRc[r] = fw[128 + c];
    }
    float FBq = filt_b[c];
    float FBr = filt_b[128 + c];

    int node = blockIdx.x;
    if (node >= N) return;
    int e0 = g_rowptr[node], e1 = g_rowptr[node + 1];
    float accq = 0.f, am0 = 0.f, am1 = 0.f, am2 = 0.f;

    for (int eb = e0; eb < e1; eb += EB) {
        int cnt = min(EB, e1 - eb);
        __syncthreads();
        if (c < cnt * 5)
            *(float4*)&s_phif[c << 2] = *(const float4*)&g_phif[(size_t)eb * NRBF + (c << 2)];
        int t = c - 80;
        if (t >= 0 && t < cnt * 3)
            s_dir[t] = g_dir[(size_t)eb * 3 + t];
        if (c < cnt) s_fcut[c] = g_fcut[eb + c];
        int u = c - 16;
        if (u >= 0 && u < cnt) s_idx[u] = idx_j[eb + u];
        __syncthreads();

        for (int i = 0; i < cnt; i++) {
            int j = s_idx[i];
            const float* xr = &x[(size_t)j * 384];
            float xq = xr[c], xR = xr[128 + c];
            float p[NRBF];
#pragma unroll
            for (int v = 0; v < 5; v++)
                *(float4*)&p[v * 4] = *(const float4*)&s_phif[i * NRBF + v * 4];
            float fc = s_fcut[i];
            float d0 = s_dir[i * 3 + 0], d1 = s_dir[i * 3 + 1], d2 = s_dir[i * 3 + 2];
            float Wq = fc * FBq, Wr = fc * FBr;
#pragma unroll
            for (int r = 0; r < NRBF; r++) {
                Wq = fmaf(p[r], WQc[r], Wq);
                Wr = fmaf(p[r], WRc[r], Wr);
            }
            accq = fmaf(Wq, xq, accq);
            float tt = Wr * xR;
            am0 = fmaf(tt, d0, am0);
            am1 = fmaf(tt, d1, am1);
            am2 = fmaf(tt, d2, am2);
        }
    }
    q[(size_t)node * 128 + c] += accq;
    size_t mb = (size_t)node * 384;
    mu_out[mb + c]       = am0;
    mu_out[mb + 128 + c] = am1;
    mu_out[mb + 256 + c] = am2;
}

// ---------------- mixing stage 1: norms, dot, build ctx ----------------
__global__ void mix1_kernel(const float* __restrict__ q, int N) {
    int t = blockIdx.x * blockDim.x + threadIdx.x;
    if (t >= N * 128) return;
    int n = t >> 7, c = t & 127;
    const float* mm = &g_mumix[(size_t)n * 768];
    float v0 = mm[c],        v1 = mm[256 + c], v2 = mm[512 + c];
    float w0 = mm[128 + c],  w1 = mm[384 + c], w2 = mm[640 + c];
    float vn = sqrtf(v0 * v0 + v1 * v1 + v2 * v2 + 1e-8f);
    g_ctx[(size_t)n * 256 + c]       = q[t];
    g_ctx[(size_t)n * 256 + 128 + c] = vn;
    g_s[t] = v0 * w0 + v1 * w1 + v2 * w2;
}

// ---------------- mixing stage 2: final per-node update ----------------
__global__ void epi2_kernel(float* __restrict__ q, float* __restrict__ mu, int N) {
    int t = blockIdx.x * blockDim.x + threadIdx.x;
    if (t >= N * 128) return;
    int n = t >> 7, c = t & 127;
    const float* xr = &g_x[(size_t)n * 384];
    float dq   = xr[c];
    float dmu  = xr[128 + c];
    float dqmu = xr[256 + c];
    q[t] += dq + dqmu * g_s[t];
    const float* mm = &g_mumix[(size_t)n * 768];
    size_t mb = (size_t)n * 384;
    mu[mb + c]       += dmu * mm[128 + c];
    mu[mb + 128 + c] += dmu * mm[384 + c];
    mu[mb + 256 + c] += dmu * mm[640 + c];
}

// ---------------- host launch ----------------
extern "C" void kernel_launch(void* const* d_in, const int* in_sizes, int n_in,
                              void* d_out, int out_size) {
    const int*   an     = (const int*)  d_in[0];
    const float* r_ij   = (const float*)d_in[1];
    const int*   idx_i  = (const int*)  d_in[2];
    const int*   idx_j  = (const int*)  d_in[3];
    const float* emb    = (const float*)d_in[4];
    const float* filt_W = (const float*)d_in[5];
    const float* filt_b = (const float*)d_in[6];
    const float* int_W1 = (const float*)d_in[7];
    const float* int_b1 = (const float*)d_in[8];
    const float* int_W2 = (const float*)d_in[9];
    const float* int_b2 = (const float*)d_in[10];
    const float* mix_W1 = (const float*)d_in[11];
    const float* mix_b1 = (const float*)d_in[12];
    const float* mix_W2 = (const float*)d_in[13];
    const float* mix_b2 = (const float*)d_in[14];
    const float* mux_W  = (const float*)d_in[15];

    int N = in_sizes[0];
    int E = in_sizes[3];

    float* q      = (float*)d_out;          // [N,128]
    float* mu_out = q + (size_t)N * 128;    // [N,3,128]

    void* pA; cudaGetSymbolAddress(&pA, g_muA);  float* muA  = (float*)pA;
    void* pH; cudaGetSymbolAddress(&pH, g_h);    float* h    = (float*)pH;
    void* pX; cudaGetSymbolAddress(&pX, g_x);    float* xbuf = (float*)pX;
    void* pM; cudaGetSymbolAddress(&pM, g_mumix);float* mumix= (float*)pM;
    void* pC; cudaGetSymbolAddress(&pC, g_ctx);  float* ctx  = (float*)pC;

    // precompute
    pre_kernel   <<<(E + 255) / 256, 256>>>(r_ij, E);
    rowptr_kernel<<<(N + 256) / 256, 256>>>(idx_i, E, N);
    init_kernel  <<<((size_t)N * 128 + 255) / 256, 256>>>(an, emb, q, N);

    for (int l = 0; l < NLAYERS; l++) {
        float* mu_in = (l & 1) ? mu_out : muA;
        float* mu_o  = (l & 1) ? muA    : mu_out;

        // interaction: h = silu(q W1 + b1); x = h W2 + b2
        {
            dim3 g(128 / 64, (N + 63) / 64);
            gemm64<1><<<g, 256>>>(q, int_W1 + (size_t)l * 128 * 128,
                                  int_b1 + l * 128, h, N, 128, 128);
        }
        {
            dim3 g(384 / 64, (N + 63) / 64);
            gemm64<0><<<g, 256>>>(h, int_W2 + (size_t)l * 128 * 384,
                                  int_b2 + l * 384, xbuf, N, 384, 128);
        }
        // edge messages + segment sum (one block per node)
        if (l == 0) {
            edge0_kernel<<<N, 128>>>(xbuf, q, mu_o, idx_j, filt_W, filt_b, N);
        } else {
            edge_kernel<<<N, 128>>>(xbuf, q, mu_in, mu_o, idx_j,
                                    filt_W, filt_b, l, N);
        }
        // mixing: mumix = mu @ mux_W (no bias), A viewed as [3N,128]
        {
            dim3 g(256 / 64, (3 * N + 63) / 64);
            gemm64<0><<<g, 256>>>(mu_o, mux_W + (size_t)l * 128 * 256,
                                  nullptr, mumix, 3 * N, 256, 128);
        }
        mix1_kernel<<<((size_t)N * 128 + 255) / 256, 256>>>(q, N);
        // h = silu(ctx mix_W1 + b1)
        {
            dim3 g(128 / 64, (N + 63) / 64);
            gemm64<1><<<g, 256>>>(ctx, mix_W1 + (size_t)l * 256 * 128,
                                  mix_b1 + l * 128, h, N, 128, 256);
        }
        // x2 = h mix_W2 + b2 (into xbuf)
        {
            dim3 g(384 / 64, (N + 63) / 64);
            gemm64<0><<<g, 256>>>(h, mix_W2 + (size_t)l * 128 * 384,
                                  mix_b2 + l * 384, xbuf, N, 384, 128);
        }
        epi2_kernel<<<((size_t)N * 128 + 255) / 256, 256>>>(q, mu_o, N);
    }
    // layer parity: l=0 in=(zero) out=d_out, l=1 in=d_out out=muA, l=2 in=muA out=d_out.
    // Final q and mu land in d_out. (q lives in d_out throughout.)
}

// round 9
// speedup vs baseline: 1.9663x; 1.0191x over previous
#include <cuda_runtime.h>
#include <math.h>

#define NRBF  20
#define MAXN  10000
#define MAXE  320000
#define NLAYERS 3
#define EB 16   // edge batch staged through smem

// ---------------- device scratch (allocation-free) ----------------
__device__ float g_dir  [MAXE * 3];
__device__ float g_phif [MAXE * NRBF];   // phi * fcut
__device__ float g_fcut [MAXE];
__device__ int   g_rowptr[MAXN + 1];
__device__ float g_x    [MAXN * 384];
__device__ float g_h    [MAXN * 128];
__device__ float g_muA  [MAXN * 384];
__device__ float g_mumix[MAXN * 768];    // [N,3,256]

// ---------------- precompute per-edge geometry + RBF ----------------
__global__ void pre_kernel(const float* __restrict__ r_ij, int E) {
    int e = blockIdx.x * blockDim.x + threadIdx.x;
    if (e >= E) return;
    float x = r_ij[e * 3 + 0];
    float y = r_ij[e * 3 + 1];
    float z = r_ij[e * 3 + 2];
    float d = sqrtf(x * x + y * y + z * z);
    float inv = 1.0f / d;
    g_dir[e * 3 + 0] = x * inv;
    g_dir[e * 3 + 1] = y * inv;
    g_dir[e * 3 + 2] = z * inv;
    float fc = (d < 5.0f) ? 0.5f * (cosf(d * 0.62831853071795864769f) + 1.0f) : 0.0f;
    g_fcut[e] = fc;
    const float delta = 5.0f / 19.0f;
    const float coeff = -0.5f / (delta * delta);
#pragma unroll
    for (int r = 0; r < NRBF; r++) {
        float diff = d - delta * (float)r;
        g_phif[e * NRBF + r] = expf(coeff * diff * diff) * fc;
    }
}

// ---------------- segment boundaries (idx_i sorted) ----------------
__global__ void rowptr_kernel(const int* __restrict__ idx_i, int E, int N) {
    int i = blockIdx.x * blockDim.x + threadIdx.x;
    if (i > N) return;
    int lo = 0, hi = E;
    while (lo < hi) {
        int mid = (lo + hi) >> 1;
        if (idx_i[mid] < i) lo = mid + 1; else hi = mid;
    }
    g_rowptr[i] = lo;
}

// ---------------- init q = embedding[an] ----------------
__global__ void init_kernel(const int* __restrict__ an, const float* __restrict__ emb,
                            float* __restrict__ q, int N) {
    int t = blockIdx.x * blockDim.x + threadIdx.x;
    if (t < N * 128) {
        int n = t >> 7, c = t & 127;
        q[t] = emb[an[n] * 128 + c];
    }
}

// ---------------- double-buffered fp32 GEMM: C = act(A[M,K] @ W[K,N] + bias) --
// BM=BN=64, BK=32, 256 threads, 4x4 per thread. N % 64 == 0, K % 32 == 0.
template <int ACT>   // 0 = none, 1 = silu
__global__ void __launch_bounds__(256)
gemm64(const float* __restrict__ A, const float* __restrict__ W,
       const float* __restrict__ bias, float* __restrict__ C,
       int M, int N, int K) {
    __shared__ float As[2][32][68];
    __shared__ float Bs[2][32][68];
    const int tid  = threadIdx.x;
    const int row0 = blockIdx.y * 64;
    const int col0 = blockIdx.x * 64;
    const int tx = tid & 15, ty = tid >> 4;

    int ar0 = tid >> 3,          ak0 = (tid & 7) << 2;
    int ar1 = (tid + 256) >> 3;
    int br0 = tid >> 4,          bc0 = (tid & 15) << 2;
    int br1 = (tid + 256) >> 4;

    const bool av0 = (row0 + ar0) < M;
    const bool av1 = (row0 + ar1) < M;
    const float* Ap0 = A + (size_t)(row0 + ar0) * K + ak0;
    const float* Ap1 = A + (size_t)(row0 + ar1) * K + ak0;
    const float* Wp0 = W + (size_t)br0 * N + col0 + bc0;
    const float* Wp1 = W + (size_t)br1 * N + col0 + bc0;

    float4 a0 = av0 ? *(const float4*)Ap0 : make_float4(0.f, 0.f, 0.f, 0.f);
    float4 a1 = av1 ? *(const float4*)Ap1 : make_float4(0.f, 0.f, 0.f, 0.f);
    float4 b0 = *(const float4*)Wp0;
    float4 b1 = *(const float4*)Wp1;
    As[0][ak0 + 0][ar0] = a0.x; As[0][ak0 + 1][ar0] = a0.y;
    As[0][ak0 + 2][ar0] = a0.z; As[0][ak0 + 3][ar0] = a0.w;
    As[0][ak0 + 0][ar1] = a1.x; As[0][ak0 + 1][ar1] = a1.y;
    As[0][ak0 + 2][ar1] = a1.z; As[0][ak0 + 3][ar1] = a1.w;
    *(float4*)&Bs[0][br0][bc0] = b0;
    *(float4*)&Bs[0][br1][bc0] = b1;
    __syncthreads();

    float acc[4][4];
#pragma unroll
    for (int i = 0; i < 4; i++)
#pragma unroll
        for (int j = 0; j < 4; j++) acc[i][j] = 0.0f;

    int buf = 0;
    for (int k0 = 32; k0 < K; k0 += 32) {
        a0 = av0 ? *(const float4*)(Ap0 + k0) : make_float4(0.f, 0.f, 0.f, 0.f);
        a1 = av1 ? *(const float4*)(Ap1 + k0) : make_float4(0.f, 0.f, 0.f, 0.f);
        b0 = *(const float4*)(Wp0 + (size_t)k0 * N);
        b1 = *(const float4*)(Wp1 + (size_t)k0 * N);
#pragma unroll
        for (int kk = 0; kk < 32; kk++) {
            float4 a = *(const float4*)&As[buf][kk][ty << 2];
            float4 b = *(const float4*)&Bs[buf][kk][tx << 2];
            acc[0][0] = fmaf(a.x, b.x, acc[0][0]); acc[0][1] = fmaf(a.x, b.y, acc[0][1]);
            acc[0][2] = fmaf(a.x, b.z, acc[0][2]); acc[0][3] = fmaf(a.x, b.w, acc[0][3]);
            acc[1][0] = fmaf(a.y, b.x, acc[1][0]); acc[1][1] = fmaf(a.y, b.y, acc[1][1]);
            acc[1][2] = fmaf(a.y, b.z, acc[1][2]); acc[1][3] = fmaf(a.y, b.w, acc[1][3]);
            acc[2][0] = fmaf(a.z, b.x, acc[2][0]); acc[2][1] = fmaf(a.z, b.y, acc[2][1]);
            acc[2][2] = fmaf(a.z, b.z, acc[2][2]); acc[2][3] = fmaf(a.z, b.w, acc[2][3]);
            acc[3][0] = fmaf(a.w, b.x, acc[3][0]); acc[3][1] = fmaf(a.w, b.y, acc[3][1]);
            acc[3][2] = fmaf(a.w, b.z, acc[3][2]); acc[3][3] = fmaf(a.w, b.w, acc[3][3]);
        }
        buf ^= 1;
        As[buf][ak0 + 0][ar0] = a0.x; As[buf][ak0 + 1][ar0] = a0.y;
        As[buf][ak0 + 2][ar0] = a0.z; As[buf][ak0 + 3][ar0] = a0.w;
        As[buf][ak0 + 0][ar1] = a1.x; As[buf][ak0 + 1][ar1] = a1.y;
        As[buf][ak0 + 2][ar1] = a1.z; As[buf][ak0 + 3][ar1] = a1.w;
        *(float4*)&Bs[buf][br0][bc0] = b0;
        *(float4*)&Bs[buf][br1][bc0] = b1;
        __syncthreads();
    }
#pragma unroll
    for (int kk = 0; kk < 32; kk++) {
        float4 a = *(const float4*)&As[buf][kk][ty << 2];
        float4 b = *(const float4*)&Bs[buf][kk][tx << 2];
        acc[0][0] = fmaf(a.x, b.x, acc[0][0]); acc[0][1] = fmaf(a.x, b.y, acc[0][1]);
        acc[0][2] = fmaf(a.x, b.z, acc[0][2]); acc[0][3] = fmaf(a.x, b.w, acc[0][3]);
        acc[1][0] = fmaf(a.y, b.x, acc[1][0]); acc[1][1] = fmaf(a.y, b.y, acc[1][1]);
        acc[1][2] = fmaf(a.y, b.z, acc[1][2]); acc[1][3] = fmaf(a.y, b.w, acc[1][3]);
        acc[2][0] = fmaf(a.z, b.x, acc[2][0]); acc[2][1] = fmaf(a.z, b.y, acc[2][1]);
        acc[2][2] = fmaf(a.z, b.z, acc[2][2]); acc[2][3] = fmaf(a.z, b.w, acc[2][3]);
        acc[3][0] = fmaf(a.w, b.x, acc[3][0]); acc[3][1] = fmaf(a.w, b.y, acc[3][1]);
        acc[3][2] = fmaf(a.w, b.z, acc[3][2]); acc[3][3] = fmaf(a.w, b.w, acc[3][3]);
    }

    float bj[4] = {0.f, 0.f, 0.f, 0.f};
    if (bias) {
#pragma unroll
        for (int j = 0; j < 4; j++) bj[j] = bias[col0 + (tx << 2) + j];
    }
#pragma unroll
    for (int i = 0; i < 4; i++) {
        int r = row0 + (ty << 2) + i;
        if (r >= M) continue;
        float4 v;
        float* pv = &v.x;
#pragma unroll
        for (int j = 0; j < 4; j++) {
            float val = acc[i][j] + bj[j];
            if (ACT == 1) val = val / (1.0f + expf(-val));
            pv[j] = val;
        }
        *(float4*)&C[(size_t)r * N + col0 + (tx << 2)] = v;
    }
}

// ---------------- ctx GEMM: h = silu(ctx @ W + b), ctx built on the fly ------
// ctx[n, k] = q[n,k] for k<128, ||mu_V[n, k-128]|| for k>=128.
// K = 256 fixed, N = 128. Same tiling as gemm64.
__device__ __forceinline__ float4 ctx_load(const float* __restrict__ q,
                                           const float* __restrict__ mumix,
                                           int n, int k, bool valid) {
    if (!valid) return make_float4(0.f, 0.f, 0.f, 0.f);
    if (k < 128) return *(const float4*)&q[(size_t)n * 128 + k];
    int c = k - 128;
    const float* b = mumix + (size_t)n * 768;
    float4 v0 = *(const float4*)&b[c];
    float4 v1 = *(const float4*)&b[256 + c];
    float4 v2 = *(const float4*)&b[512 + c];
    float4 r;
    r.x = sqrtf(v0.x * v0.x + v1.x * v1.x + v2.x * v2.x + 1e-8f);
    r.y = sqrtf(v0.y * v0.y + v1.y * v1.y + v2.y * v2.y + 1e-8f);
    r.z = sqrtf(v0.z * v0.z + v1.z * v1.z + v2.z * v2.z + 1e-8f);
    r.w = sqrtf(v0.w * v0.w + v1.w * v1.w + v2.w * v2.w + 1e-8f);
    return r;
}

__global__ void __launch_bounds__(256)
gemm_ctx(const float* __restrict__ q, const float* __restrict__ mumix,
         const float* __restrict__ W, const float* __restrict__ bias,
         float* __restrict__ C, int M) {
    const int Nn = 128, K = 256;
    __shared__ float As[2][32][68];
    __shared__ float Bs[2][32][68];
    const int tid  = threadIdx.x;
    const int row0 = blockIdx.y * 64;
    const int col0 = blockIdx.x * 64;
    const int tx = tid & 15, ty = tid >> 4;

    int ar0 = tid >> 3,          ak0 = (tid & 7) << 2;
    int ar1 = (tid + 256) >> 3;
    int br0 = tid >> 4,          bc0 = (tid & 15) << 2;
    int br1 = (tid + 256) >> 4;

    const bool av0 = (row0 + ar0) < M;
    const bool av1 = (row0 + ar1) < M;
    const float* Wp0 = W + (size_t)br0 * Nn + col0 + bc0;
    const float* Wp1 = W + (size_t)br1 * Nn + col0 + bc0;

    float4 a0 = ctx_load(q, mumix, row0 + ar0, ak0, av0);
    float4 a1 = ctx_load(q, mumix, row0 + ar1, ak0, av1);
    float4 b0 = *(const float4*)Wp0;
    float4 b1 = *(const float4*)Wp1;
    As[0][ak0 + 0][ar0] = a0.x; As[0][ak0 + 1][ar0] = a0.y;
    As[0][ak0 + 2][ar0] = a0.z; As[0][ak0 + 3][ar0] = a0.w;
    As[0][ak0 + 0][ar1] = a1.x; As[0][ak0 + 1][ar1] = a1.y;
    As[0][ak0 + 2][ar1] = a1.z; As[0][ak0 + 3][ar1] = a1.w;
    *(float4*)&Bs[0][br0][bc0] = b0;
    *(float4*)&Bs[0][br1][bc0] = b1;
    __syncthreads();

    float acc[4][4];
#pragma unroll
    for (int i = 0; i < 4; i++)
#pragma unroll
        for (int j = 0; j < 4; j++) acc[i][j] = 0.0f;

    int buf = 0;
    for (int k0 = 32; k0 < K; k0 += 32) {
        a0 = ctx_load(q, mumix, row0 + ar0, k0 + ak0, av0);
        a1 = ctx_load(q, mumix, row0 + ar1, k0 + ak0, av1);
        b0 = *(const float4*)(Wp0 + (size_t)k0 * Nn);
        b1 = *(const float4*)(Wp1 + (size_t)k0 * Nn);
#pragma unroll
        for (int kk = 0; kk < 32; kk++) {
            float4 a = *(const float4*)&As[buf][kk][ty << 2];
            float4 b = *(const float4*)&Bs[buf][kk][tx << 2];
            acc[0][0] = fmaf(a.x, b.x, acc[0][0]); acc[0][1] = fmaf(a.x, b.y, acc[0][1]);
            acc[0][2] = fmaf(a.x, b.z, acc[0][2]); acc[0][3] = fmaf(a.x, b.w, acc[0][3]);
            acc[1][0] = fmaf(a.y, b.x, acc[1][0]); acc[1][1] = fmaf(a.y, b.y, acc[1][1]);
            acc[1][2] = fmaf(a.y, b.z, acc[1][2]); acc[1][3] = fmaf(a.y, b.w, acc[1][3]);
            acc[2][0] = fmaf(a.z, b.x, acc[2][0]); acc[2][1] = fmaf(a.z, b.y, acc[2][1]);
            acc[2][2] = fmaf(a.z, b.z, acc[2][2]); acc[2][3] = fmaf(a.z, b.w, acc[2][3]);
            acc[3][0] = fmaf(a.w, b.x, acc[3][0]); acc[3][1] = fmaf(a.w, b.y, acc[3][1]);
            acc[3][2] = fmaf(a.w, b.z, acc[3][2]); acc[3][3] = fmaf(a.w, b.w, acc[3][3]);
        }
        buf ^= 1;
        As[buf][ak0 + 0][ar0] = a0.x; As[buf][ak0 + 1][ar0] = a0.y;
        As[buf][ak0 + 2][ar0] = a0.z; As[buf][ak0 + 3][ar0] = a0.w;
        As[buf][ak0 + 0][ar1] = a1.x; As[buf][ak0 + 1][ar1] = a1.y;
        As[buf][ak0 + 2][ar1] = a1.z; As[buf][ak0 + 3][ar1] = a1.w;
        *(float4*)&Bs[buf][br0][bc0] = b0;
        *(float4*)&Bs[buf][br1][bc0] = b1;
        __syncthreads();
    }
#pragma unroll
    for (int kk = 0; kk < 32; kk++) {
        float4 a = *(const float4*)&As[buf][kk][ty << 2];
        float4 b = *(const float4*)&Bs[buf][kk][tx << 2];
        acc[0][0] = fmaf(a.x, b.x, acc[0][0]); acc[0][1] = fmaf(a.x, b.y, acc[0][1]);
        acc[0][2] = fmaf(a.x, b.z, acc[0][2]); acc[0][3] = fmaf(a.x, b.w, acc[0][3]);
        acc[1][0] = fmaf(a.y, b.x, acc[1][0]); acc[1][1] = fmaf(a.y, b.y, acc[1][1]);
        acc[1][2] = fmaf(a.y, b.z, acc[1][2]); acc[1][3] = fmaf(a.y, b.w, acc[1][3]);
        acc[2][0] = fmaf(a.z, b.x, acc[2][0]); acc[2][1] = fmaf(a.z, b.y, acc[2][1]);
        acc[2][2] = fmaf(a.z, b.z, acc[2][2]); acc[2][3] = fmaf(a.z, b.w, acc[2][3]);
        acc[3][0] = fmaf(a.w, b.x, acc[3][0]); acc[3][1] = fmaf(a.w, b.y, acc[3][1]);
        acc[3][2] = fmaf(a.w, b.z, acc[3][2]); acc[3][3] = fmaf(a.w, b.w, acc[3][3]);
    }

    float bj[4];
#pragma unroll
    for (int j = 0; j < 4; j++) bj[j] = bias[col0 + (tx << 2) + j];
#pragma unroll
    for (int i = 0; i < 4; i++) {
        int r = row0 + (ty << 2) + i;
        if (r >= M) continue;
        float4 v;
        float* pv = &v.x;
#pragma unroll
        for (int j = 0; j < 4; j++) {
            float val = acc[i][j] + bj[j];
            val = val / (1.0f + expf(-val));
            pv[j] = val;
        }
        *(float4*)&C[(size_t)r * Nn + col0 + (tx << 2)] = v;
    }
}

// ---------------- edge message + segment-sum kernel (general layers) --------
__global__ void __launch_bounds__(128)
edge_kernel(const float* __restrict__ x,
            float* __restrict__ q,
            const float* __restrict__ mu_in,
            float* __restrict__ mu_out,
            const int* __restrict__ idx_j,
            const float* __restrict__ filt_W,
            const float* __restrict__ filt_b,
            int layer, int N) {
    __shared__ __align__(16) float s_phif[EB * NRBF];
    __shared__ float s_dir[EB * 3];
    __shared__ float s_fcut[EB];
    __shared__ int   s_idx[EB];

    int c = threadIdx.x;   // 0..127
    int layOff = layer * 384;
    float WQc[NRBF], WRc[NRBF], WMc[NRBF];
#pragma unroll
    for (int r = 0; r < NRBF; r++) {
        const float* fw = &filt_W[r * (NLAYERS * 384) + layOff];
        WQc[r] = fw[c];
        WRc[r] = fw[128 + c];
        WMc[r] = fw[256 + c];
    }
    float FBq = filt_b[layOff + c];
    float FBr = filt_b[layOff + 128 + c];
    float FBm = filt_b[layOff + 256 + c];

    int node = blockIdx.x;
    if (node >= N) return;
    int e0 = g_rowptr[node], e1 = g_rowptr[node + 1];
    float accq = 0.f, am0 = 0.f, am1 = 0.f, am2 = 0.f;

    for (int eb = e0; eb < e1; eb += EB) {
        int cnt = min(EB, e1 - eb);
        __syncthreads();
        if (c < cnt * 5)
            *(float4*)&s_phif[c << 2] = *(const float4*)&g_phif[(size_t)eb * NRBF + (c << 2)];
        int t = c - 80;
        if (t >= 0 && t < cnt * 3)
            s_dir[t] = g_dir[(size_t)eb * 3 + t];
        if (c < cnt) s_fcut[c] = g_fcut[eb + c];
        int u = c - 16;
        if (u >= 0 && u < cnt) s_idx[u] = idx_j[eb + u];
        __syncthreads();

        for (int i = 0; i < cnt; i++) {
            int j = s_idx[i];
            const float* xr = &x[(size_t)j * 384];
            const float* mj = &mu_in[(size_t)j * 384];
            float xq = xr[c], xR = xr[128 + c], xM = xr[256 + c];
            float m0 = mj[c], m1 = mj[128 + c], m2 = mj[256 + c];
            float p[NRBF];
#pragma unroll
            for (int v = 0; v < 5; v++)
                *(float4*)&p[v * 4] = *(const float4*)&s_phif[i * NRBF + v * 4];
            float fc = s_fcut[i];
            float d0 = s_dir[i * 3 + 0], d1 = s_dir[i * 3 + 1], d2 = s_dir[i * 3 + 2];
            float Wq = fc * FBq, Wr = fc * FBr, Wm = fc * FBm;
#pragma unroll
            for (int r = 0; r < NRBF; r++) {
                Wq = fmaf(p[r], WQc[r], Wq);
                Wr = fmaf(p[r], WRc[r], Wr);
                Wm = fmaf(p[r], WMc[r], Wm);
            }
            accq = fmaf(Wq, xq, accq);
            float tt  = Wr * xR;
            float wmx = Wm * xM;
            am0 = fmaf(tt, d0, fmaf(wmx, m0, am0));
            am1 = fmaf(tt, d1, fmaf(wmx, m1, am1));
            am2 = fmaf(tt, d2, fmaf(wmx, m2, am2));
        }
    }
    q[(size_t)node * 128 + c] += accq;
    size_t mb = (size_t)node * 384;
    mu_out[mb + c]       = mu_in[mb + c]       + am0;
    mu_out[mb + 128 + c] = mu_in[mb + 128 + c] + am1;
    mu_out[mb + 256 + c] = mu_in[mb + 256 + c] + am2;
}

// ---------------- layer-0 edge kernel: mu_in == 0 everywhere ----------------
__global__ void __launch_bounds__(128)
edge0_kernel(const float* __restrict__ x,
             float* __restrict__ q,
             float* __restrict__ mu_out,
             const int* __restrict__ idx_j,
             const float* __restrict__ filt_W,
             const float* __restrict__ filt_b,
             int N) {
    __shared__ __align__(16) float s_phif[EB * NRBF];
    __shared__ float s_dir[EB * 3];
    __shared__ float s_fcut[EB];
    __shared__ int   s_idx[EB];

    int c = threadIdx.x;
    float WQc[NRBF], WRc[NRBF];
#pragma unroll
    for (int r = 0; r < NRBF; r++) {
        const float* fw = &filt_W[r * (NLAYERS * 384)];
        WQc[r] = fw[c];
        WRc[r] = fw[128 + c];
    }
    float FBq = filt_b[c];
    float FBr = filt_b[128 + c];

    int node = blockIdx.x;
    if (node >= N) return;
    int e0 = g_rowptr[node], e1 = g_rowptr[node + 1];
    float accq = 0.f, am0 = 0.f, am1 = 0.f, am2 = 0.f;

    for (int eb = e0; eb < e1; eb += EB) {
        int cnt = min(EB, e1 - eb);
        __syncthreads();
        if (c < cnt * 5)
            *(float4*)&s_phif[c << 2] = *(const float4*)&g_phif[(size_t)eb * NRBF + (c << 2)];
        int t = c - 80;
        if (t >= 0 && t < cnt * 3)
            s_dir[t] = g_dir[(size_t)eb * 3 + t];
        if (c < cnt) s_fcut[c] = g_fcut[eb + c];
        int u = c - 16;
        if (u >= 0 && u < cnt) s_idx[u] = idx_j[eb + u];
        __syncthreads();

        for (int i = 0; i < cnt; i++) {
            int j = s_idx[i];
            const float* xr = &x[(size_t)j * 384];
            float xq = xr[c], xR = xr[128 + c];
            float p[NRBF];
#pragma unroll
            for (int v = 0; v < 5; v++)
                *(float4*)&p[v * 4] = *(const float4*)&s_phif[i * NRBF + v * 4];
            float fc = s_fcut[i];
            float d0 = s_dir[i * 3 + 0], d1 = s_dir[i * 3 + 1], d2 = s_dir[i * 3 + 2];
            float Wq = fc * FBq, Wr = fc * FBr;
#pragma unroll
            for (int r = 0; r < NRBF; r++) {
                Wq = fmaf(p[r], WQc[r], Wq);
                Wr = fmaf(p[r], WRc[r], Wr);
            }
            accq = fmaf(Wq, xq, accq);
            float tt = Wr * xR;
            am0 = fmaf(tt, d0, am0);
            am1 = fmaf(tt, d1, am1);
            am2 = fmaf(tt, d2, am2);
        }
    }
    q[(size_t)node * 128 + c] += accq;
    size_t mb = (size_t)node * 384;
    mu_out[mb + c]       = am0;
    mu_out[mb + 128 + c] = am1;
    mu_out[mb + 256 + c] = am2;
}

// ---------------- final per-node update (s computed inline) ----------------
__global__ void epi2_kernel(float* __restrict__ q, float* __restrict__ mu, int N) {
    int t = blockIdx.x * blockDim.x + threadIdx.x;
    if (t >= N * 128) return;
    int n = t >> 7, c = t & 127;
    const float* xr = &g_x[(size_t)n * 384];
    float dq   = xr[c];
    float dmu  = xr[128 + c];
    float dqmu = xr[256 + c];
    const float* mm = &g_mumix[(size_t)n * 768];
    float v0 = mm[c],       v1 = mm[256 + c], v2 = mm[512 + c];
    float w0 = mm[128 + c], w1 = mm[384 + c], w2 = mm[640 + c];
    float s = v0 * w0 + v1 * w1 + v2 * w2;
    q[t] += dq + dqmu * s;
    size_t mb = (size_t)n * 384;
    mu[mb + c]       += dmu * w0;
    mu[mb + 128 + c] += dmu * w1;
    mu[mb + 256 + c] += dmu * w2;
}

// ---------------- host launch ----------------
extern "C" void kernel_launch(void* const* d_in, const int* in_sizes, int n_in,
                              void* d_out, int out_size) {
    const int*   an     = (const int*)  d_in[0];
    const float* r_ij   = (const float*)d_in[1];
    const int*   idx_i  = (const int*)  d_in[2];
    const int*   idx_j  = (const int*)  d_in[3];
    const float* emb    = (const float*)d_in[4];
    const float* filt_W = (const float*)d_in[5];
    const float* filt_b = (const float*)d_in[6];
    const float* int_W1 = (const float*)d_in[7];
    const float* int_b1 = (const float*)d_in[8];
    const float* int_W2 = (const float*)d_in[9];
    const float* int_b2 = (const float*)d_in[10];
    const float* mix_W1 = (const float*)d_in[11];
    const float* mix_b1 = (const float*)d_in[12];
    const float* mix_W2 = (const float*)d_in[13];
    const float* mix_b2 = (const float*)d_in[14];
    const float* mux_W  = (const float*)d_in[15];

    int N = in_sizes[0];
    int E = in_sizes[3];

    float* q      = (float*)d_out;          // [N,128]
    float* mu_out = q + (size_t)N * 128;    // [N,3,128]

    void* pA; cudaGetSymbolAddress(&pA, g_muA);  float* muA  = (float*)pA;
    void* pH; cudaGetSymbolAddress(&pH, g_h);    float* h    = (float*)pH;
    void* pX; cudaGetSymbolAddress(&pX, g_x);    float* xbuf = (float*)pX;
    void* pM; cudaGetSymbolAddress(&pM, g_mumix);float* mumix= (float*)pM;

    // precompute
    pre_kernel   <<<(E + 255) / 256, 256>>>(r_ij, E);
    rowptr_kernel<<<(N + 256) / 256, 256>>>(idx_i, E, N);
    init_kernel  <<<((size_t)N * 128 + 255) / 256, 256>>>(an, emb, q, N);

    for (int l = 0; l < NLAYERS; l++) {
        float* mu_in = (l & 1) ? mu_out : muA;
        float* mu_o  = (l & 1) ? muA    : mu_out;

        // interaction: h = silu(q W1 + b1); x = h W2 + b2
        {
            dim3 g(128 / 64, (N + 63) / 64);
            gemm64<1><<<g, 256>>>(q, int_W1 + (size_t)l * 128 * 128,
                                  int_b1 + l * 128, h, N, 128, 128);
        }
        {
            dim3 g(384 / 64, (N + 63) / 64);
            gemm64<0><<<g, 256>>>(h, int_W2 + (size_t)l * 128 * 384,
                                  int_b2 + l * 384, xbuf, N, 384, 128);
        }
        // edge messages + segment sum (one block per node)
        if (l == 0) {
            edge0_kernel<<<N, 128>>>(xbuf, q, mu_o, idx_j, filt_W, filt_b, N);
        } else {
            edge_kernel<<<N, 128>>>(xbuf, q, mu_in, mu_o, idx_j,
                                    filt_W, filt_b, l, N);
        }
        // mixing: mumix = mu @ mux_W (no bias), A viewed as [3N,128]
        {
            dim3 g(256 / 64, (3 * N + 63) / 64);
            gemm64<0><<<g, 256>>>(mu_o, mux_W + (size_t)l * 128 * 256,
                                  nullptr, mumix, 3 * N, 256, 128);
        }
        // h = silu(ctx mix_W1 + b1), ctx built on the fly from q + mumix norms
        {
            dim3 g(128 / 64, (N + 63) / 64);
            gemm_ctx<<<g, 256>>>(q, mumix, mix_W1 + (size_t)l * 256 * 128,
                                 mix_b1 + l * 128, h, N);
        }
        // x2 = h mix_W2 + b2 (into xbuf)
        {
            dim3 g(384 / 64, (N + 63) / 64);
            gemm64<0><<<g, 256>>>(h, mix_W2 + (size_t)l * 128 * 384,
                                  mix_b2 + l * 384, xbuf, N, 384, 128);
        }
        epi2_kernel<<<((size_t)N * 128 + 255) / 256, 256>>>(q, mu_o, N);
    }
    // layer parity: l=0 in=(zero) out=d_out, l=1 in=d_out out=muA, l=2 in=muA out=d_out.
    // Final q and mu land in d_out. (q lives in d_out throughout.)
}